// round 12
// baseline (speedup 1.0000x reference)
#include <cuda_runtime.h>
#include <cuda_fp16.h>
#include <cstdint>

#define NROI 4000
#define CCH  64
#define FH   240
#define FW   240
#define NPIX (FH*FW)
#define NBT  (NPIX / 64)   // 900 transpose blocks

// ---------------- scratch (no allocations allowed) ----------------
__device__ __align__(16) __half2 g_fmTh[NPIX * 32];   // HWC fp16 fm (7.4 MB)
__device__ __align__(16) __half  g_pooledh[3 * NROI * CCH]; // pooled feats fp16
__device__ float g_gpart[NBT * CCH];       // per-block channel partial sums
__device__ float g_bp1eff[128];            // bp1 + head(g) @ P1[192:256]
// fp16 transposed weights, [n][k] layout (B col-major fragments)
__device__ __align__(16) __half g_W1t[128 * 64];
__device__ __align__(16) __half g_W2t[64 * 128];
__device__ __align__(16) __half g_P1t[128 * 192];
__device__ __align__(16) __half g_P2t[64 * 128];

// ---------------- mma.sync m16n8k16 f16 -> f32 ----------------
__device__ __forceinline__ void mma_f16(float* c,
                                        unsigned a0, unsigned a1, unsigned a2, unsigned a3,
                                        unsigned b0, unsigned b1) {
    asm volatile(
        "mma.sync.aligned.m16n8k16.row.col.f32.f16.f16.f32 "
        "{%0,%1,%2,%3}, {%4,%5,%6,%7}, {%8,%9}, {%0,%1,%2,%3};\n"
        : "+f"(c[0]), "+f"(c[1]), "+f"(c[2]), "+f"(c[3])
        : "r"(a0), "r"(a1), "r"(a2), "r"(a3), "r"(b0), "r"(b1));
}

// ---------------- 1) transpose + gmean partials + weight prep (fused) ----------------
__global__ void transpose_prep_kernel(const float* __restrict__ fm,
                                      const float* __restrict__ W1, const float* __restrict__ W2,
                                      const float* __restrict__ P1, const float* __restrict__ P2) {
    int b = blockIdx.x;
    int tid = threadIdx.x;
    if (b >= NBT) {
        // weight conversion: 48 blocks x 256 thr x 4 elems = 49152
        int base = (b - NBT) * 1024;
        #pragma unroll
        for (int q = 0; q < 4; q++) {
            int idx = base + q * 256 + tid;
            if (idx < 8192) {                       // W1t[128][64]
                int n = idx >> 6, k = idx & 63;
                g_W1t[idx] = __float2half(W1[k * 128 + n]);
            } else if (idx < 16384) {               // W2t[64][128]
                int i = idx - 8192;
                int n = i >> 7, k = i & 127;
                g_W2t[i] = __float2half(W2[k * 64 + n]);
            } else if (idx < 40960) {               // P1t[128][192]
                int i = idx - 16384;
                int n = i / 192, k = i - n * 192;
                g_P1t[i] = __float2half(P1[k * 128 + n]);
            } else if (idx < 49152) {               // P2t[64][128]
                int i = idx - 40960;
                int n = i >> 7, k = i & 127;
                g_P2t[i] = __float2half(P2[k * 64 + n]);
            }
        }
        return;
    }
    __shared__ float tile[64][65];
    int pix0 = b * 64;
    int lane = tid & 63;
    int grp  = tid >> 6;
    #pragma unroll
    for (int c = grp; c < 64; c += 4)
        tile[c][lane] = fm[c * NPIX + pix0 + lane];
    __syncthreads();
    int c2 = tid & 31;
    int pg = tid >> 5;
    #pragma unroll
    for (int p = pg; p < 64; p += 8)
        g_fmTh[(pix0 + p) * 32 + c2] =
            __floats2half2_rn(tile[2 * c2][p], tile[2 * c2 + 1][p]);
    if (tid < 64) {
        float s = 0.f;
        #pragma unroll 16
        for (int p = 0; p < 64; p++) s += tile[tid][p];
        g_gpart[b * 64 + tid] = s;
    }
}

// ---------------- 2) reduce gmean + fold head(g) into bp1 ----------------
__global__ void head_const_kernel(const float* __restrict__ W1, const float* __restrict__ b1,
                                  const float* __restrict__ W2, const float* __restrict__ b2,
                                  const float* __restrict__ P1, const float* __restrict__ bp1) {
    __shared__ float gs[64];
    __shared__ float part[2][64];
    __shared__ float t[128];
    __shared__ float hg[64];
    int tid = threadIdx.x;  // 128 threads
    {
        int ch = tid & 63;
        int half = tid >> 6;
        int b0 = half * (NBT / 2);
        int b1e = b0 + (NBT / 2);
        float s = 0.f;
        for (int b = b0; b < b1e; b++) s += g_gpart[b * 64 + ch];
        part[half][ch] = s;
    }
    __syncthreads();
    if (tid < 64)
        gs[tid] = (part[0][tid] + part[1][tid]) * (1.0f / (float)NPIX);
    __syncthreads();
    float a = b1[tid];
    #pragma unroll 8
    for (int c = 0; c < 64; c++) a = fmaf(gs[c], W1[c * 128 + tid], a);
    t[tid] = fmaxf(a, 0.f);
    __syncthreads();
    if (tid < 64) {
        float a2 = b2[tid];
        #pragma unroll 8
        for (int k = 0; k < 128; k++) a2 = fmaf(t[k], W2[k * 64 + tid], a2);
        hg[tid] = fmaxf(a2, 0.f);
    }
    __syncthreads();
    float be = bp1[tid];
    #pragma unroll 8
    for (int c = 0; c < 64; c++) be = fmaf(hg[c], P1[(192 + c) * 128 + tid], be);
    g_bp1eff[tid] = be;
}

// ---------------- 3) pooling: 4 samples/warp-iter, HFMA2 bilinear -> fp16 out ----------------
template<int S>
__device__ __forceinline__ void pool_roi_v(int n, int lane,
                                           const float* __restrict__ boxes,
                                           __half* __restrict__ outb) {
    constexpr int SS = S * S;
    int sub = lane >> 3;
    int cl  = lane & 7;

    float bx1 = __ldg(&boxes[n * 4 + 0]);
    float by1 = __ldg(&boxes[n * 4 + 1]);
    float bx2 = __ldg(&boxes[n * 4 + 2]);
    float by2 = __ldg(&boxes[n * 4 + 3]);
    float nx1 = bx1 * (2.0f / 960.0f) - 1.0f;
    float ny1 = by1 * (2.0f / 960.0f) - 1.0f;
    float nx2 = bx2 * (2.0f / 960.0f) - 1.0f;
    float ny2 = by2 * (2.0f / 960.0f) - 1.0f;
    float cx = (nx1 + nx2) * 0.5f;
    float cy = (ny1 + ny2) * 0.5f;
    float w  = fmaxf(nx2 - nx1, 1e-6f);
    float h  = fmaxf(ny2 - ny1, 1e-6f);
    float stepx = w * (120.0f / (float)S);
    float stepy = h * (120.0f / (float)S);
    float ixb = fmaf(w * 60.0f, (1.0f / (float)S - 1.0f), fmaf(cx, 120.0f, 119.5f));
    float iyb = fmaf(h * 60.0f, (1.0f / (float)S - 1.0f), fmaf(cy, 120.0f, 119.5f));

    float acc[8];
    #pragma unroll
    for (int k = 0; k < 8; k++) acc[k] = 0.f;

    const uint4* fm4 = (const uint4*)g_fmTh;

    #pragma unroll 2
    for (int base = 0; base < SS; base += 4) {
        int samp = base + sub;
        bool alive = (samp < SS);
        int sc = alive ? samp : 0;
        int i = sc / S;
        int j = sc - i * S;
        float ix = fmaf((float)j, stepx, ixb);
        float iy = fmaf((float)i, stepy, iyb);
        float x0f = floorf(ix), y0f = floorf(iy);
        float dx = ix - x0f, dy = iy - y0f;
        int x0 = (int)x0f, y0 = (int)y0f;
        int x1 = x0 + 1,   y1 = y0 + 1;
        float wx0 = ((unsigned)x0 < FW) ? (1.f - dx) : 0.f;
        float wx1 = ((unsigned)x1 < FW) ? dx : 0.f;
        float wy0 = (alive && (unsigned)y0 < FH) ? (1.f - dy) : 0.f;
        float wy1 = (alive && (unsigned)y1 < FH) ? dy : 0.f;
        int xc0 = max(0, min(x0, FW - 1));
        int xc1 = max(0, min(x1, FW - 1));
        int yc0 = max(0, min(y0, FH - 1));
        int yc1 = max(0, min(y1, FH - 1));
        int r0 = yc0 * FW, r1 = yc1 * FW;
        uint4 q00 = __ldg(&fm4[(r0 + xc0) * 8 + cl]);
        uint4 q01 = __ldg(&fm4[(r0 + xc1) * 8 + cl]);
        uint4 q10 = __ldg(&fm4[(r1 + xc0) * 8 + cl]);
        uint4 q11 = __ldg(&fm4[(r1 + xc1) * 8 + cl]);
        __half2 h00 = __float2half2_rn(wy0 * wx0);
        __half2 h01 = __float2half2_rn(wy0 * wx1);
        __half2 h10 = __float2half2_rn(wy1 * wx0);
        __half2 h11 = __float2half2_rn(wy1 * wx1);
        const __half2* f00 = (const __half2*)&q00;
        const __half2* f01 = (const __half2*)&q01;
        const __half2* f10 = (const __half2*)&q10;
        const __half2* f11 = (const __half2*)&q11;
        #pragma unroll
        for (int k = 0; k < 4; k++) {
            __half2 s = __hmul2(h00, f00[k]);
            s = __hfma2(h01, f01[k], s);
            s = __hfma2(h10, f10[k], s);
            s = __hfma2(h11, f11[k], s);
            float2 fs = __half22float2(s);
            acc[2 * k]     += fs.x;
            acc[2 * k + 1] += fs.y;
        }
    }

    #pragma unroll
    for (int k = 0; k < 8; k++) {
        acc[k] += __shfl_down_sync(0xffffffffu, acc[k], 16);
        acc[k] += __shfl_down_sync(0xffffffffu, acc[k], 8);
    }
    if (sub == 0) {
        const float inv = 1.0f / (float)SS;
        __half2 p[4];
        #pragma unroll
        for (int k = 0; k < 4; k++)
            p[k] = __floats2half2_rn(acc[2 * k] * inv, acc[2 * k + 1] * inv);
        *(uint4*)&outb[(size_t)n * 64 + cl * 8] = *(uint4*)p;
    }
}

__global__ void pool_all_kernel(const float* __restrict__ boxes) {
    int tid  = threadIdx.x;
    int lane = tid & 31;
    int warp = tid >> 5;
    int task = blockIdx.x * 8 + warp;
    if (task < NROI) {
        pool_roi_v<11>(task, lane, boxes, g_pooledh + (size_t)2 * NROI * CCH);
    } else if (task < 2 * NROI) {
        pool_roi_v<7>(task - NROI, lane, boxes, g_pooledh + (size_t)NROI * CCH);
    } else {
        pool_roi_v<3>(task - 2 * NROI, lane, boxes, g_pooledh);
    }
}

// ---------------- 4) fused MLP via tensor cores ----------------
// 16 rows/block, 250 blocks, 256 thr (8 warps). All heads kept in smem; no gmem round trip.
#define TS_STRIDE 136   // halves; rows 4 banks apart -> conflict-free fragment reads
#define HS_STRIDE 72    // halves; same property
__global__ __launch_bounds__(256)
void mlp_mma_kernel(const float* __restrict__ b1, const float* __restrict__ b2,
                    const float* __restrict__ bp2, float* __restrict__ out) {
    __shared__ __half Tsh[16 * TS_STRIDE];        // 4352 B
    __shared__ __half hS[3 * 16 * HS_STRIDE];     // 6912 B
    int tid  = threadIdx.x;
    int w    = tid >> 5;
    int lane = tid & 31;
    int g    = lane >> 2;
    int tig  = lane & 3;
    int row0 = blockIdx.x * 16;
    int r_lo = row0 + g;

    // ---- per-scale heads ----
    for (int scale = 0; scale < 3; scale++) {
        const __half* X = g_pooledh + (size_t)scale * NROI * CCH;

        // phase A: T = relu(X@W1 + b1)  [16x128]; warp w covers ntiles 2w,2w+1
        float c[2][4];
        #pragma unroll
        for (int j = 0; j < 2; j++)
            #pragma unroll
            for (int q = 0; q < 4; q++) c[j][q] = 0.f;
        #pragma unroll
        for (int k0 = 0; k0 < 64; k0 += 16) {
            const __half* ar = X + (size_t)r_lo * 64 + k0 + 2 * tig;
            unsigned a0 = *(const unsigned*)ar;
            unsigned a1 = *(const unsigned*)(ar + 8 * 64);
            unsigned a2 = *(const unsigned*)(ar + 8);
            unsigned a3 = *(const unsigned*)(ar + 8 * 64 + 8);
            #pragma unroll
            for (int j = 0; j < 2; j++) {
                const __half* bp = g_W1t + (w * 16 + j * 8 + g) * 64 + k0 + 2 * tig;
                unsigned b0 = *(const unsigned*)bp;
                unsigned b1r = *(const unsigned*)(bp + 8);
                mma_f16(c[j], a0, a1, a2, a3, b0, b1r);
            }
        }
        #pragma unroll
        for (int j = 0; j < 2; j++) {
            int col = w * 16 + j * 8 + 2 * tig;
            float2 bb = *(const float2*)&b1[col];
            __half2 lo = __floats2half2_rn(fmaxf(c[j][0] + bb.x, 0.f),
                                           fmaxf(c[j][1] + bb.y, 0.f));
            __half2 hi = __floats2half2_rn(fmaxf(c[j][2] + bb.x, 0.f),
                                           fmaxf(c[j][3] + bb.y, 0.f));
            *(__half2*)&Tsh[g * TS_STRIDE + col] = lo;
            *(__half2*)&Tsh[(g + 8) * TS_STRIDE + col] = hi;
        }
        __syncthreads();

        // phase B: h = relu(T@W2 + b2)  [16x64]; warp w covers ntile w
        float d[4];
        #pragma unroll
        for (int q = 0; q < 4; q++) d[q] = 0.f;
        #pragma unroll
        for (int k0 = 0; k0 < 128; k0 += 16) {
            const __half* ar = &Tsh[g * TS_STRIDE + k0 + 2 * tig];
            unsigned a0 = *(const unsigned*)ar;
            unsigned a1 = *(const unsigned*)(ar + 8 * TS_STRIDE);
            unsigned a2 = *(const unsigned*)(ar + 8);
            unsigned a3 = *(const unsigned*)(ar + 8 * TS_STRIDE + 8);
            const __half* bp = g_W2t + (w * 8 + g) * 128 + k0 + 2 * tig;
            unsigned b0 = *(const unsigned*)bp;
            unsigned b1r = *(const unsigned*)(bp + 8);
            mma_f16(d, a0, a1, a2, a3, b0, b1r);
        }
        {
            int col = w * 8 + 2 * tig;
            float2 bb = *(const float2*)&b2[col];
            __half2 lo = __floats2half2_rn(fmaxf(d[0] + bb.x, 0.f),
                                           fmaxf(d[1] + bb.y, 0.f));
            __half2 hi = __floats2half2_rn(fmaxf(d[2] + bb.x, 0.f),
                                           fmaxf(d[3] + bb.y, 0.f));
            __half* hdst = hS + scale * 16 * HS_STRIDE;
            *(__half2*)&hdst[g * HS_STRIDE + col] = lo;
            *(__half2*)&hdst[(g + 8) * HS_STRIDE + col] = hi;
        }
        __syncthreads();   // Tsh free for next scale; hS[scale] visible
    }

    // ---- final layer 1: T = relu(cat(h)@P1 + bp1eff)  [16x128], K=192 ----
    float c[2][4];
    #pragma unroll
    for (int j = 0; j < 2; j++)
        #pragma unroll
        for (int q = 0; q < 4; q++) c[j][q] = 0.f;
    #pragma unroll
    for (int k0 = 0; k0 < 192; k0 += 16) {
        int chunk = k0 >> 6;
        int kin = k0 & 63;
        const __half* ar = hS + chunk * 16 * HS_STRIDE + g * HS_STRIDE + kin + 2 * tig;
        unsigned a0 = *(const unsigned*)ar;
        unsigned a1 = *(const unsigned*)(ar + 8 * HS_STRIDE);
        unsigned a2 = *(const unsigned*)(ar + 8);
        unsigned a3 = *(const unsigned*)(ar + 8 * HS_STRIDE + 8);
        #pragma unroll
        for (int j = 0; j < 2; j++) {
            const __half* bp = g_P1t + (w * 16 + j * 8 + g) * 192 + k0 + 2 * tig;
            unsigned b0 = *(const unsigned*)bp;
            unsigned b1r = *(const unsigned*)(bp + 8);
            mma_f16(c[j], a0, a1, a2, a3, b0, b1r);
        }
    }
    #pragma unroll
    for (int j = 0; j < 2; j++) {
        int col = w * 16 + j * 8 + 2 * tig;
        float2 bb = *(const float2*)&g_bp1eff[col];
        __half2 lo = __floats2half2_rn(fmaxf(c[j][0] + bb.x, 0.f),
                                       fmaxf(c[j][1] + bb.y, 0.f));
        __half2 hi = __floats2half2_rn(fmaxf(c[j][2] + bb.x, 0.f),
                                       fmaxf(c[j][3] + bb.y, 0.f));
        *(__half2*)&Tsh[g * TS_STRIDE + col] = lo;
        *(__half2*)&Tsh[(g + 8) * TS_STRIDE + col] = hi;
    }
    __syncthreads();

    // ---- final layer 2: out = relu(T@P2 + bp2)  [16x64] fp32 ----
    float d[4];
    #pragma unroll
    for (int q = 0; q < 4; q++) d[q] = 0.f;
    #pragma unroll
    for (int k0 = 0; k0 < 128; k0 += 16) {
        const __half* ar = &Tsh[g * TS_STRIDE + k0 + 2 * tig];
        unsigned a0 = *(const unsigned*)ar;
        unsigned a1 = *(const unsigned*)(ar + 8 * TS_STRIDE);
        unsigned a2 = *(const unsigned*)(ar + 8);
        unsigned a3 = *(const unsigned*)(ar + 8 * TS_STRIDE + 8);
        const __half* bp = g_P2t + (w * 8 + g) * 128 + k0 + 2 * tig;
        unsigned b0 = *(const unsigned*)bp;
        unsigned b1r = *(const unsigned*)(bp + 8);
        mma_f16(d, a0, a1, a2, a3, b0, b1r);
    }
    {
        int col = w * 8 + 2 * tig;
        float2 bb = *(const float2*)&bp2[col];
        float2 lo, hi;
        lo.x = fmaxf(d[0] + bb.x, 0.f);
        lo.y = fmaxf(d[1] + bb.y, 0.f);
        hi.x = fmaxf(d[2] + bb.x, 0.f);
        hi.y = fmaxf(d[3] + bb.y, 0.f);
        *(float2*)&out[(size_t)r_lo * 64 + col] = lo;
        *(float2*)&out[(size_t)(r_lo + 8) * 64 + col] = hi;
    }
}

// ---------------- launch ----------------
extern "C" void kernel_launch(void* const* d_in, const int* in_sizes, int n_in,
                              void* d_out, int out_size) {
    const float* fm    = (const float*)d_in[0];
    const float* boxes = (const float*)d_in[1];
    const float* W1    = (const float*)d_in[2];
    const float* b1    = (const float*)d_in[3];
    const float* W2    = (const float*)d_in[4];
    const float* b2    = (const float*)d_in[5];
    const float* P1    = (const float*)d_in[6];
    const float* bp1   = (const float*)d_in[7];
    const float* P2    = (const float*)d_in[8];
    const float* bp2   = (const float*)d_in[9];
    float* out = (float*)d_out;

    transpose_prep_kernel<<<NBT + 48, 256>>>(fm, W1, W2, P1, P2);
    head_const_kernel<<<1, 128>>>(W1, b1, W2, b2, P1, bp1);

    const int PB = (3 * NROI) / 8;  // 1500 blocks
    pool_all_kernel<<<PB, 256>>>(boxes);

    mlp_mma_kernel<<<NROI / 16, 256>>>(b1, b2, bp2, out);
}

// round 13
// speedup vs baseline: 1.2455x; 1.2455x over previous
#include <cuda_runtime.h>
#include <cuda_fp16.h>
#include <cstdint>

#define NROI 4000
#define CCH  64
#define FH   240
#define FW   240
#define NPIX (FH*FW)
#define NBT  (NPIX / 64)   // 900 transpose blocks

// ---------------- scratch (no allocations allowed) ----------------
__device__ __align__(16) __half2 g_fmTh[NPIX * 32];   // HWC fp16 fm (7.4 MB)
__device__ __align__(16) __half  g_pooledh[3 * NROI * CCH]; // pooled feats fp16
__device__ float g_gpart[NBT * CCH];       // per-block channel partial sums
__device__ float g_bp1eff[128];            // bp1 + head(g) @ P1[192:256]
// fp16 transposed weights, [n][k] layout (B col-major fragments)
__device__ __align__(16) __half g_W1t[128 * 64];
__device__ __align__(16) __half g_W2t[64 * 128];
__device__ __align__(16) __half g_P1t[128 * 192];
__device__ __align__(16) __half g_P2t[64 * 128];

// ---------------- mma.sync m16n8k16 f16 -> f32 ----------------
__device__ __forceinline__ void mma_f16(float* c,
                                        unsigned a0, unsigned a1, unsigned a2, unsigned a3,
                                        unsigned b0, unsigned b1) {
    asm volatile(
        "mma.sync.aligned.m16n8k16.row.col.f32.f16.f16.f32 "
        "{%0,%1,%2,%3}, {%4,%5,%6,%7}, {%8,%9}, {%0,%1,%2,%3};\n"
        : "+f"(c[0]), "+f"(c[1]), "+f"(c[2]), "+f"(c[3])
        : "r"(a0), "r"(a1), "r"(a2), "r"(a3), "r"(b0), "r"(b1));
}

// ---------------- 1) transpose + gmean partials + weight prep (fused) ----------------
__global__ void transpose_prep_kernel(const float* __restrict__ fm,
                                      const float* __restrict__ W1, const float* __restrict__ W2,
                                      const float* __restrict__ P1, const float* __restrict__ P2) {
    int b = blockIdx.x;
    int tid = threadIdx.x;
    if (b >= NBT) {
        // weight conversion: 48 blocks x 256 thr x 4 elems = 49152
        int base = (b - NBT) * 1024;
        #pragma unroll
        for (int q = 0; q < 4; q++) {
            int idx = base + q * 256 + tid;
            if (idx < 8192) {                       // W1t[128][64]
                int n = idx >> 6, k = idx & 63;
                g_W1t[idx] = __float2half(W1[k * 128 + n]);
            } else if (idx < 16384) {               // W2t[64][128]
                int i = idx - 8192;
                int n = i >> 7, k = i & 127;
                g_W2t[i] = __float2half(W2[k * 64 + n]);
            } else if (idx < 40960) {               // P1t[128][192]
                int i = idx - 16384;
                int n = i / 192, k = i - n * 192;
                g_P1t[i] = __float2half(P1[k * 128 + n]);
            } else if (idx < 49152) {               // P2t[64][128]
                int i = idx - 40960;
                int n = i >> 7, k = i & 127;
                g_P2t[i] = __float2half(P2[k * 64 + n]);
            }
        }
        return;
    }
    __shared__ float tile[64][65];
    int pix0 = b * 64;
    int lane = tid & 63;
    int grp  = tid >> 6;
    #pragma unroll
    for (int c = grp; c < 64; c += 4)
        tile[c][lane] = fm[c * NPIX + pix0 + lane];
    __syncthreads();
    int c2 = tid & 31;
    int pg = tid >> 5;
    #pragma unroll
    for (int p = pg; p < 64; p += 8)
        g_fmTh[(pix0 + p) * 32 + c2] =
            __floats2half2_rn(tile[2 * c2][p], tile[2 * c2 + 1][p]);
    if (tid < 64) {
        float s = 0.f;
        #pragma unroll 16
        for (int p = 0; p < 64; p++) s += tile[tid][p];
        g_gpart[b * 64 + tid] = s;
    }
}

// ---------------- 2) reduce gmean + fold head(g) into bp1 ----------------
__global__ void head_const_kernel(const float* __restrict__ W1, const float* __restrict__ b1,
                                  const float* __restrict__ W2, const float* __restrict__ b2,
                                  const float* __restrict__ P1, const float* __restrict__ bp1) {
    __shared__ float gs[64];
    __shared__ float part[2][64];
    __shared__ float t[128];
    __shared__ float hg[64];
    int tid = threadIdx.x;  // 128 threads
    {
        int ch = tid & 63;
        int half = tid >> 6;
        int b0 = half * (NBT / 2);
        int b1e = b0 + (NBT / 2);
        float s = 0.f;
        for (int b = b0; b < b1e; b++) s += g_gpart[b * 64 + ch];
        part[half][ch] = s;
    }
    __syncthreads();
    if (tid < 64)
        gs[tid] = (part[0][tid] + part[1][tid]) * (1.0f / (float)NPIX);
    __syncthreads();
    float a = b1[tid];
    #pragma unroll 8
    for (int c = 0; c < 64; c++) a = fmaf(gs[c], W1[c * 128 + tid], a);
    t[tid] = fmaxf(a, 0.f);
    __syncthreads();
    if (tid < 64) {
        float a2 = b2[tid];
        #pragma unroll 8
        for (int k = 0; k < 128; k++) a2 = fmaf(t[k], W2[k * 64 + tid], a2);
        hg[tid] = fmaxf(a2, 0.f);
    }
    __syncthreads();
    float be = bp1[tid];
    #pragma unroll 8
    for (int c = 0; c < 64; c++) be = fmaf(hg[c], P1[(192 + c) * 128 + tid], be);
    g_bp1eff[tid] = be;
}

// ---------------- 3) pooling: 4 samples/warp-iter, HFMA2 bilinear -> fp16 out ----------------
template<int S>
__device__ __forceinline__ void pool_roi_v(int n, int lane,
                                           const float* __restrict__ boxes,
                                           __half* __restrict__ outb) {
    constexpr int SS = S * S;
    int sub = lane >> 3;
    int cl  = lane & 7;

    float bx1 = __ldg(&boxes[n * 4 + 0]);
    float by1 = __ldg(&boxes[n * 4 + 1]);
    float bx2 = __ldg(&boxes[n * 4 + 2]);
    float by2 = __ldg(&boxes[n * 4 + 3]);
    float nx1 = bx1 * (2.0f / 960.0f) - 1.0f;
    float ny1 = by1 * (2.0f / 960.0f) - 1.0f;
    float nx2 = bx2 * (2.0f / 960.0f) - 1.0f;
    float ny2 = by2 * (2.0f / 960.0f) - 1.0f;
    float cx = (nx1 + nx2) * 0.5f;
    float cy = (ny1 + ny2) * 0.5f;
    float w  = fmaxf(nx2 - nx1, 1e-6f);
    float h  = fmaxf(ny2 - ny1, 1e-6f);
    float stepx = w * (120.0f / (float)S);
    float stepy = h * (120.0f / (float)S);
    float ixb = fmaf(w * 60.0f, (1.0f / (float)S - 1.0f), fmaf(cx, 120.0f, 119.5f));
    float iyb = fmaf(h * 60.0f, (1.0f / (float)S - 1.0f), fmaf(cy, 120.0f, 119.5f));

    float acc[8];
    #pragma unroll
    for (int k = 0; k < 8; k++) acc[k] = 0.f;

    const uint4* fm4 = (const uint4*)g_fmTh;

    #pragma unroll 2
    for (int base = 0; base < SS; base += 4) {
        int samp = base + sub;
        bool alive = (samp < SS);
        int sc = alive ? samp : 0;
        int i = sc / S;
        int j = sc - i * S;
        float ix = fmaf((float)j, stepx, ixb);
        float iy = fmaf((float)i, stepy, iyb);
        float x0f = floorf(ix), y0f = floorf(iy);
        float dx = ix - x0f, dy = iy - y0f;
        int x0 = (int)x0f, y0 = (int)y0f;
        int x1 = x0 + 1,   y1 = y0 + 1;
        float wx0 = ((unsigned)x0 < FW) ? (1.f - dx) : 0.f;
        float wx1 = ((unsigned)x1 < FW) ? dx : 0.f;
        float wy0 = (alive && (unsigned)y0 < FH) ? (1.f - dy) : 0.f;
        float wy1 = (alive && (unsigned)y1 < FH) ? dy : 0.f;
        int xc0 = max(0, min(x0, FW - 1));
        int xc1 = max(0, min(x1, FW - 1));
        int yc0 = max(0, min(y0, FH - 1));
        int yc1 = max(0, min(y1, FH - 1));
        int r0 = yc0 * FW, r1 = yc1 * FW;
        uint4 q00 = __ldg(&fm4[(r0 + xc0) * 8 + cl]);
        uint4 q01 = __ldg(&fm4[(r0 + xc1) * 8 + cl]);
        uint4 q10 = __ldg(&fm4[(r1 + xc0) * 8 + cl]);
        uint4 q11 = __ldg(&fm4[(r1 + xc1) * 8 + cl]);
        __half2 h00 = __float2half2_rn(wy0 * wx0);
        __half2 h01 = __float2half2_rn(wy0 * wx1);
        __half2 h10 = __float2half2_rn(wy1 * wx0);
        __half2 h11 = __float2half2_rn(wy1 * wx1);
        const __half2* f00 = (const __half2*)&q00;
        const __half2* f01 = (const __half2*)&q01;
        const __half2* f10 = (const __half2*)&q10;
        const __half2* f11 = (const __half2*)&q11;
        #pragma unroll
        for (int k = 0; k < 4; k++) {
            __half2 s = __hmul2(h00, f00[k]);
            s = __hfma2(h01, f01[k], s);
            s = __hfma2(h10, f10[k], s);
            s = __hfma2(h11, f11[k], s);
            float2 fs = __half22float2(s);
            acc[2 * k]     += fs.x;
            acc[2 * k + 1] += fs.y;
        }
    }

    #pragma unroll
    for (int k = 0; k < 8; k++) {
        acc[k] += __shfl_down_sync(0xffffffffu, acc[k], 16);
        acc[k] += __shfl_down_sync(0xffffffffu, acc[k], 8);
    }
    if (sub == 0) {
        const float inv = 1.0f / (float)SS;
        __half2 p[4];
        #pragma unroll
        for (int k = 0; k < 4; k++)
            p[k] = __floats2half2_rn(acc[2 * k] * inv, acc[2 * k + 1] * inv);
        *(uint4*)&outb[(size_t)n * 64 + cl * 8] = *(uint4*)p;
    }
}

__global__ void pool_all_kernel(const float* __restrict__ boxes) {
    int tid  = threadIdx.x;
    int lane = tid & 31;
    int warp = tid >> 5;
    int task = blockIdx.x * 8 + warp;
    if (task < NROI) {
        pool_roi_v<11>(task, lane, boxes, g_pooledh + (size_t)2 * NROI * CCH);
    } else if (task < 2 * NROI) {
        pool_roi_v<7>(task - NROI, lane, boxes, g_pooledh + (size_t)NROI * CCH);
    } else {
        pool_roi_v<3>(task - 2 * NROI, lane, boxes, g_pooledh);
    }
}

// ---------------- 4) fused MLP via tensor cores, weights staged in smem ----------------
// 16 rows/block, 250 blocks, 256 thr (8 warps).
// Padded smem strides (halves): rows land on distinct banks for fragment reads.
#define TS_STRIDE 136   // Tsh: K=128 rows
#define HS_STRIDE 72    // hS:  K=64 rows
#define W1_STRIDE 72    // W1s: 128 rows x 64 halves
#define W2_STRIDE 136   // W2s: 64 rows x 128 halves
#define P1_STRIDE 200   // P1s: 128 rows x 192 halves
#define P2_STRIDE 136   // P2s: 64 rows x 128 halves
// weight buffer (halves): heads need W1s(128*72=9216)+W2s(64*136=8704)=17920;
// P1s needs 128*200=25600 (max); P2s needs 8704.
#define WBUF_HALVES 25600
#define SMEM_MLP_HALVES (WBUF_HALVES + 16*TS_STRIDE + 3*16*HS_STRIDE)  // 25600+2176+3456

__global__ __launch_bounds__(256)
void mlp_mma_kernel(const float* __restrict__ b1, const float* __restrict__ b2,
                    const float* __restrict__ bp2, float* __restrict__ out) {
    extern __shared__ __half sh[];
    __half* Wbuf = sh;                       // 25600 halves, reused per phase
    __half* Tsh  = sh + WBUF_HALVES;         // 16*136
    __half* hS   = Tsh + 16 * TS_STRIDE;     // 3*16*72

    int tid  = threadIdx.x;
    int w    = tid >> 5;
    int lane = tid & 31;
    int g    = lane >> 2;
    int tig  = lane & 3;
    int row0 = blockIdx.x * 16;
    int r_lo = row0 + g;

    __half* W1s = Wbuf;                      // 128 x W1_STRIDE
    __half* W2s = Wbuf + 128 * W1_STRIDE;    // 64 x W2_STRIDE

    // ---- stage W1s + W2s ----
    {
        // W1t: 128 rows x 8 uint4
        const uint4* src = (const uint4*)g_W1t;
        for (int i = tid; i < 1024; i += 256) {
            int r = i >> 3, q = i & 7;
            ((uint4*)&W1s[r * W1_STRIDE])[q] = src[r * 8 + q];
        }
        // W2t: 64 rows x 16 uint4
        const uint4* src2 = (const uint4*)g_W2t;
        for (int i = tid; i < 1024; i += 256) {
            int r = i >> 4, q = i & 15;
            ((uint4*)&W2s[r * W2_STRIDE])[q] = src2[r * 16 + q];
        }
    }
    __syncthreads();

    // ---- per-scale heads ----
    for (int scale = 0; scale < 3; scale++) {
        const __half* X = g_pooledh + (size_t)scale * NROI * CCH;

        // phase A: T = relu(X@W1 + b1)  [16x128]; warp w covers ntiles 2w,2w+1
        float c[2][4];
        #pragma unroll
        for (int j = 0; j < 2; j++)
            #pragma unroll
            for (int q = 0; q < 4; q++) c[j][q] = 0.f;
        #pragma unroll
        for (int k0 = 0; k0 < 64; k0 += 16) {
            const __half* ar = X + (size_t)r_lo * 64 + k0 + 2 * tig;
            unsigned a0 = *(const unsigned*)ar;
            unsigned a1 = *(const unsigned*)(ar + 8 * 64);
            unsigned a2 = *(const unsigned*)(ar + 8);
            unsigned a3 = *(const unsigned*)(ar + 8 * 64 + 8);
            #pragma unroll
            for (int j = 0; j < 2; j++) {
                const __half* bp = W1s + (w * 16 + j * 8 + g) * W1_STRIDE + k0 + 2 * tig;
                unsigned b0 = *(const unsigned*)bp;
                unsigned b1r = *(const unsigned*)(bp + 8);
                mma_f16(c[j], a0, a1, a2, a3, b0, b1r);
            }
        }
        #pragma unroll
        for (int j = 0; j < 2; j++) {
            int col = w * 16 + j * 8 + 2 * tig;
            float2 bb = *(const float2*)&b1[col];
            __half2 lo = __floats2half2_rn(fmaxf(c[j][0] + bb.x, 0.f),
                                           fmaxf(c[j][1] + bb.y, 0.f));
            __half2 hi = __floats2half2_rn(fmaxf(c[j][2] + bb.x, 0.f),
                                           fmaxf(c[j][3] + bb.y, 0.f));
            *(__half2*)&Tsh[g * TS_STRIDE + col] = lo;
            *(__half2*)&Tsh[(g + 8) * TS_STRIDE + col] = hi;
        }
        __syncthreads();

        // phase B: h = relu(T@W2 + b2)  [16x64]; warp w covers ntile w
        float d[4];
        #pragma unroll
        for (int q = 0; q < 4; q++) d[q] = 0.f;
        #pragma unroll
        for (int k0 = 0; k0 < 128; k0 += 16) {
            const __half* ar = &Tsh[g * TS_STRIDE + k0 + 2 * tig];
            unsigned a0 = *(const unsigned*)ar;
            unsigned a1 = *(const unsigned*)(ar + 8 * TS_STRIDE);
            unsigned a2 = *(const unsigned*)(ar + 8);
            unsigned a3 = *(const unsigned*)(ar + 8 * TS_STRIDE + 8);
            const __half* bp = W2s + (w * 8 + g) * W2_STRIDE + k0 + 2 * tig;
            unsigned b0 = *(const unsigned*)bp;
            unsigned b1r = *(const unsigned*)(bp + 8);
            mma_f16(d, a0, a1, a2, a3, b0, b1r);
        }
        {
            int col = w * 8 + 2 * tig;
            float2 bb = *(const float2*)&b2[col];
            __half2 lo = __floats2half2_rn(fmaxf(d[0] + bb.x, 0.f),
                                           fmaxf(d[1] + bb.y, 0.f));
            __half2 hi = __floats2half2_rn(fmaxf(d[2] + bb.x, 0.f),
                                           fmaxf(d[3] + bb.y, 0.f));
            __half* hdst = hS + scale * 16 * HS_STRIDE;
            *(__half2*)&hdst[g * HS_STRIDE + col] = lo;
            *(__half2*)&hdst[(g + 8) * HS_STRIDE + col] = hi;
        }
        __syncthreads();   // Tsh free for next scale; hS[scale] visible
    }

    // ---- stage P1s (overwrites W1s/W2s; last sync guarantees reads done) ----
    {
        const uint4* src = (const uint4*)g_P1t;   // 128 rows x 24 uint4
        for (int i = tid; i < 3072; i += 256) {
            int r = i / 24, q = i - r * 24;
            ((uint4*)&Wbuf[r * P1_STRIDE])[q] = src[r * 24 + q];
        }
    }
    __syncthreads();

    // ---- final layer 1: T = relu(cat(h)@P1 + bp1eff)  [16x128], K=192 ----
    float c[2][4];
    #pragma unroll
    for (int j = 0; j < 2; j++)
        #pragma unroll
        for (int q = 0; q < 4; q++) c[j][q] = 0.f;
    #pragma unroll
    for (int k0 = 0; k0 < 192; k0 += 16) {
        int chunk = k0 >> 6;
        int kin = k0 & 63;
        const __half* ar = hS + chunk * 16 * HS_STRIDE + g * HS_STRIDE + kin + 2 * tig;
        unsigned a0 = *(const unsigned*)ar;
        unsigned a1 = *(const unsigned*)(ar + 8 * HS_STRIDE);
        unsigned a2 = *(const unsigned*)(ar + 8);
        unsigned a3 = *(const unsigned*)(ar + 8 * HS_STRIDE + 8);
        #pragma unroll
        for (int j = 0; j < 2; j++) {
            const __half* bp = Wbuf + (w * 16 + j * 8 + g) * P1_STRIDE + k0 + 2 * tig;
            unsigned b0 = *(const unsigned*)bp;
            unsigned b1r = *(const unsigned*)(bp + 8);
            mma_f16(c[j], a0, a1, a2, a3, b0, b1r);
        }
    }
    #pragma unroll
    for (int j = 0; j < 2; j++) {
        int col = w * 16 + j * 8 + 2 * tig;
        float2 bb = *(const float2*)&g_bp1eff[col];
        __half2 lo = __floats2half2_rn(fmaxf(c[j][0] + bb.x, 0.f),
                                       fmaxf(c[j][1] + bb.y, 0.f));
        __half2 hi = __floats2half2_rn(fmaxf(c[j][2] + bb.x, 0.f),
                                       fmaxf(c[j][3] + bb.y, 0.f));
        *(__half2*)&Tsh[g * TS_STRIDE + col] = lo;
        *(__half2*)&Tsh[(g + 8) * TS_STRIDE + col] = hi;
    }
    __syncthreads();

    // ---- stage P2s (overwrites Wbuf; P1 reads done) ----
    {
        const uint4* src = (const uint4*)g_P2t;   // 64 rows x 16 uint4
        for (int i = tid; i < 1024; i += 256) {
            int r = i >> 4, q = i & 15;
            ((uint4*)&Wbuf[r * P2_STRIDE])[q] = src[r * 16 + q];
        }
    }
    __syncthreads();

    // ---- final layer 2: out = relu(T@P2 + bp2)  [16x64] fp32 ----
    float d[4];
    #pragma unroll
    for (int q = 0; q < 4; q++) d[q] = 0.f;
    #pragma unroll
    for (int k0 = 0; k0 < 128; k0 += 16) {
        const __half* ar = &Tsh[g * TS_STRIDE + k0 + 2 * tig];
        unsigned a0 = *(const unsigned*)ar;
        unsigned a1 = *(const unsigned*)(ar + 8 * TS_STRIDE);
        unsigned a2 = *(const unsigned*)(ar + 8);
        unsigned a3 = *(const unsigned*)(ar + 8 * TS_STRIDE + 8);
        const __half* bp = Wbuf + (w * 8 + g) * P2_STRIDE + k0 + 2 * tig;
        unsigned b0 = *(const unsigned*)bp;
        unsigned b1r = *(const unsigned*)(bp + 8);
        mma_f16(d, a0, a1, a2, a3, b0, b1r);
    }
    {
        int col = w * 8 + 2 * tig;
        float2 bb = *(const float2*)&bp2[col];
        float2 lo, hi;
        lo.x = fmaxf(d[0] + bb.x, 0.f);
        lo.y = fmaxf(d[1] + bb.y, 0.f);
        hi.x = fmaxf(d[2] + bb.x, 0.f);
        hi.y = fmaxf(d[3] + bb.y, 0.f);
        *(float2*)&out[(size_t)r_lo * 64 + col] = lo;
        *(float2*)&out[(size_t)(r_lo + 8) * 64 + col] = hi;
    }
}

// ---------------- launch ----------------
extern "C" void kernel_launch(void* const* d_in, const int* in_sizes, int n_in,
                              void* d_out, int out_size) {
    const float* fm    = (const float*)d_in[0];
    const float* boxes = (const float*)d_in[1];
    const float* W1    = (const float*)d_in[2];
    const float* b1    = (const float*)d_in[3];
    const float* W2    = (const float*)d_in[4];
    const float* b2    = (const float*)d_in[5];
    const float* P1    = (const float*)d_in[6];
    const float* bp1   = (const float*)d_in[7];
    const float* P2    = (const float*)d_in[8];
    const float* bp2   = (const float*)d_in[9];
    float* out = (float*)d_out;

    const int SMEM_MLP = SMEM_MLP_HALVES * 2;   // 62464 B
    cudaFuncSetAttribute(mlp_mma_kernel, cudaFuncAttributeMaxDynamicSharedMemorySize, SMEM_MLP);

    transpose_prep_kernel<<<NBT + 48, 256>>>(fm, W1, W2, P1, P2);
    head_const_kernel<<<1, 128>>>(W1, b1, W2, b2, P1, bp1);

    const int PB = (3 * NROI) / 8;  // 1500 blocks
    pool_all_kernel<<<PB, 256>>>(boxes);

    mlp_mma_kernel<<<NROI / 16, 256, SMEM_MLP>>>(b1, b2, bp2, out);
}

// round 15
// speedup vs baseline: 1.8864x; 1.5146x over previous
#include <cuda_runtime.h>
#include <cuda_fp16.h>
#include <cstdint>

#define NROI 4000
#define CCH  64
#define FH   240
#define FW   240
#define NPIX (FH*FW)
#define NBT  (NPIX / 64)   // 900 transpose blocks

// ---------------- scratch (no allocations allowed) ----------------
__device__ __align__(16) __half2 g_fmTh[NPIX * 32];   // HWC fp16 fm (7.4 MB)
__device__ __align__(16) __half  g_pooledh[3 * NROI * CCH]; // pooled feats fp16
__device__ float g_gpart[NBT * CCH];       // per-block channel partial sums
__device__ float g_bp1eff[128];            // bp1 + head(g) @ P1[192:256]
// fp16 transposed weights, [n][k] layout (B col-major fragments)
__device__ __align__(16) __half g_W1t[128 * 64];
__device__ __align__(16) __half g_W2t[64 * 128];
__device__ __align__(16) __half g_P1t[128 * 192];
__device__ __align__(16) __half g_P2t[64 * 128];

// ---------------- mma.sync m16n8k16 f16 -> f32 ----------------
__device__ __forceinline__ void mma_f16(float* c,
                                        unsigned a0, unsigned a1, unsigned a2, unsigned a3,
                                        unsigned b0, unsigned b1) {
    asm volatile(
        "mma.sync.aligned.m16n8k16.row.col.f32.f16.f16.f32 "
        "{%0,%1,%2,%3}, {%4,%5,%6,%7}, {%8,%9}, {%0,%1,%2,%3};\n"
        : "+f"(c[0]), "+f"(c[1]), "+f"(c[2]), "+f"(c[3])
        : "r"(a0), "r"(a1), "r"(a2), "r"(a3), "r"(b0), "r"(b1));
}

// ---------------- 1) transpose + gmean partials + weight prep (fused) ----------------
__global__ void transpose_prep_kernel(const float* __restrict__ fm,
                                      const float* __restrict__ W1, const float* __restrict__ W2,
                                      const float* __restrict__ P1, const float* __restrict__ P2) {
    int b = blockIdx.x;
    int tid = threadIdx.x;
    if (b >= NBT) {
        // weight conversion: 48 blocks x 256 thr x 4 elems = 49152
        int base = (b - NBT) * 1024;
        #pragma unroll
        for (int q = 0; q < 4; q++) {
            int idx = base + q * 256 + tid;
            if (idx < 8192) {                       // W1t[128][64]
                int n = idx >> 6, k = idx & 63;
                g_W1t[idx] = __float2half(W1[k * 128 + n]);
            } else if (idx < 16384) {               // W2t[64][128]
                int i = idx - 8192;
                int n = i >> 7, k = i & 127;
                g_W2t[i] = __float2half(W2[k * 64 + n]);
            } else if (idx < 40960) {               // P1t[128][192]
                int i = idx - 16384;
                int n = i / 192, k = i - n * 192;
                g_P1t[i] = __float2half(P1[k * 128 + n]);
            } else if (idx < 49152) {               // P2t[64][128]
                int i = idx - 40960;
                int n = i >> 7, k = i & 127;
                g_P2t[i] = __float2half(P2[k * 64 + n]);
            }
        }
        return;
    }
    __shared__ float tile[64][65];
    int pix0 = b * 64;
    int lane = tid & 63;
    int grp  = tid >> 6;
    #pragma unroll
    for (int c = grp; c < 64; c += 4)
        tile[c][lane] = fm[c * NPIX + pix0 + lane];
    __syncthreads();
    int c2 = tid & 31;
    int pg = tid >> 5;
    #pragma unroll
    for (int p = pg; p < 64; p += 8)
        g_fmTh[(pix0 + p) * 32 + c2] =
            __floats2half2_rn(tile[2 * c2][p], tile[2 * c2 + 1][p]);
    if (tid < 64) {
        float s = 0.f;
        #pragma unroll 16
        for (int p = 0; p < 64; p++) s += tile[tid][p];
        g_gpart[b * 64 + tid] = s;
    }
}

// ---------------- 2) reduce gmean + fold head(g) into bp1 ----------------
__global__ void head_const_kernel(const float* __restrict__ W1, const float* __restrict__ b1,
                                  const float* __restrict__ W2, const float* __restrict__ b2,
                                  const float* __restrict__ P1, const float* __restrict__ bp1) {
    __shared__ float gs[64];
    __shared__ float part[2][64];
    __shared__ float t[128];
    __shared__ float hg[64];
    int tid = threadIdx.x;  // 128 threads
    {
        int ch = tid & 63;
        int half = tid >> 6;
        int b0 = half * (NBT / 2);
        int b1e = b0 + (NBT / 2);
        float s = 0.f;
        for (int b = b0; b < b1e; b++) s += g_gpart[b * 64 + ch];
        part[half][ch] = s;
    }
    __syncthreads();
    if (tid < 64)
        gs[tid] = (part[0][tid] + part[1][tid]) * (1.0f / (float)NPIX);
    __syncthreads();
    float a = b1[tid];
    #pragma unroll 8
    for (int c = 0; c < 64; c++) a = fmaf(gs[c], W1[c * 128 + tid], a);
    t[tid] = fmaxf(a, 0.f);
    __syncthreads();
    if (tid < 64) {
        float a2 = b2[tid];
        #pragma unroll 8
        for (int k = 0; k < 128; k++) a2 = fmaf(t[k], W2[k * 64 + tid], a2);
        hg[tid] = fmaxf(a2, 0.f);
    }
    __syncthreads();
    float be = bp1[tid];
    #pragma unroll 8
    for (int c = 0; c < 64; c++) be = fmaf(hg[c], P1[(192 + c) * 128 + tid], be);
    g_bp1eff[tid] = be;
}

// ---------------- 3) pooling: 4 samples/warp-iter, HFMA2 bilinear -> fp16 out ----------------
template<int S>
__device__ __forceinline__ void pool_roi_v(int n, int lane,
                                           const float* __restrict__ boxes,
                                           __half* __restrict__ outb) {
    constexpr int SS = S * S;
    int sub = lane >> 3;
    int cl  = lane & 7;

    float bx1 = __ldg(&boxes[n * 4 + 0]);
    float by1 = __ldg(&boxes[n * 4 + 1]);
    float bx2 = __ldg(&boxes[n * 4 + 2]);
    float by2 = __ldg(&boxes[n * 4 + 3]);
    float nx1 = bx1 * (2.0f / 960.0f) - 1.0f;
    float ny1 = by1 * (2.0f / 960.0f) - 1.0f;
    float nx2 = bx2 * (2.0f / 960.0f) - 1.0f;
    float ny2 = by2 * (2.0f / 960.0f) - 1.0f;
    float cx = (nx1 + nx2) * 0.5f;
    float cy = (ny1 + ny2) * 0.5f;
    float w  = fmaxf(nx2 - nx1, 1e-6f);
    float h  = fmaxf(ny2 - ny1, 1e-6f);
    float stepx = w * (120.0f / (float)S);
    float stepy = h * (120.0f / (float)S);
    float ixb = fmaf(w * 60.0f, (1.0f / (float)S - 1.0f), fmaf(cx, 120.0f, 119.5f));
    float iyb = fmaf(h * 60.0f, (1.0f / (float)S - 1.0f), fmaf(cy, 120.0f, 119.5f));

    float acc[8];
    #pragma unroll
    for (int k = 0; k < 8; k++) acc[k] = 0.f;

    const uint4* fm4 = (const uint4*)g_fmTh;

    #pragma unroll 2
    for (int base = 0; base < SS; base += 4) {
        int samp = base + sub;
        bool alive = (samp < SS);
        int sc = alive ? samp : 0;
        int i = sc / S;
        int j = sc - i * S;
        float ix = fmaf((float)j, stepx, ixb);
        float iy = fmaf((float)i, stepy, iyb);
        float x0f = floorf(ix), y0f = floorf(iy);
        float dx = ix - x0f, dy = iy - y0f;
        int x0 = (int)x0f, y0 = (int)y0f;
        int x1 = x0 + 1,   y1 = y0 + 1;
        float wx0 = ((unsigned)x0 < FW) ? (1.f - dx) : 0.f;
        float wx1 = ((unsigned)x1 < FW) ? dx : 0.f;
        float wy0 = (alive && (unsigned)y0 < FH) ? (1.f - dy) : 0.f;
        float wy1 = (alive && (unsigned)y1 < FH) ? dy : 0.f;
        int xc0 = max(0, min(x0, FW - 1));
        int xc1 = max(0, min(x1, FW - 1));
        int yc0 = max(0, min(y0, FH - 1));
        int yc1 = max(0, min(y1, FH - 1));
        int r0 = yc0 * FW, r1 = yc1 * FW;
        uint4 q00 = __ldg(&fm4[(r0 + xc0) * 8 + cl]);
        uint4 q01 = __ldg(&fm4[(r0 + xc1) * 8 + cl]);
        uint4 q10 = __ldg(&fm4[(r1 + xc0) * 8 + cl]);
        uint4 q11 = __ldg(&fm4[(r1 + xc1) * 8 + cl]);
        __half2 h00 = __float2half2_rn(wy0 * wx0);
        __half2 h01 = __float2half2_rn(wy0 * wx1);
        __half2 h10 = __float2half2_rn(wy1 * wx0);
        __half2 h11 = __float2half2_rn(wy1 * wx1);
        const __half2* f00 = (const __half2*)&q00;
        const __half2* f01 = (const __half2*)&q01;
        const __half2* f10 = (const __half2*)&q10;
        const __half2* f11 = (const __half2*)&q11;
        #pragma unroll
        for (int k = 0; k < 4; k++) {
            __half2 s = __hmul2(h00, f00[k]);
            s = __hfma2(h01, f01[k], s);
            s = __hfma2(h10, f10[k], s);
            s = __hfma2(h11, f11[k], s);
            float2 fs = __half22float2(s);
            acc[2 * k]     += fs.x;
            acc[2 * k + 1] += fs.y;
        }
    }

    #pragma unroll
    for (int k = 0; k < 8; k++) {
        acc[k] += __shfl_down_sync(0xffffffffu, acc[k], 16);
        acc[k] += __shfl_down_sync(0xffffffffu, acc[k], 8);
    }
    if (sub == 0) {
        const float inv = 1.0f / (float)SS;
        __half2 p[4];
        #pragma unroll
        for (int k = 0; k < 4; k++)
            p[k] = __floats2half2_rn(acc[2 * k] * inv, acc[2 * k + 1] * inv);
        *(uint4*)&outb[(size_t)n * 64 + cl * 8] = *(uint4*)p;
    }
}

__global__ void pool_all_kernel(const float* __restrict__ boxes) {
    int tid  = threadIdx.x;
    int lane = tid & 31;
    int warp = tid >> 5;
    int task = blockIdx.x * 8 + warp;
    if (task < NROI) {
        pool_roi_v<11>(task, lane, boxes, g_pooledh + (size_t)2 * NROI * CCH);
    } else if (task < 2 * NROI) {
        pool_roi_v<7>(task - NROI, lane, boxes, g_pooledh + (size_t)NROI * CCH);
    } else {
        pool_roi_v<3>(task - 2 * NROI, lane, boxes, g_pooledh);
    }
}

// ---------------- 4) fused MLP via tensor cores, EVERYTHING smem-resident ----------------
// 16 rows/block, 250 blocks, 256 thr (8 warps).
// All operands staged once up-front; double-buffered Tsh; 6 syncs total.
#define TS_STRIDE 136
#define HS_STRIDE 72
#define W1_STRIDE 72
#define W2_STRIDE 136
#define P1_STRIDE 200
#define P2_STRIDE 136
// smem layout (halves):
#define OFF_W1   0                     // 128*72  = 9216  (P2 reuses this later)
#define OFF_W2   9216                  // 64*136  = 8704
#define OFF_P1   17920                 // 128*200 = 25600
#define OFF_TS   43520                 // 2 * 16*136 = 4352 (double buffer)
#define OFF_HS   47872                 // 3*16*72 = 3456
#define OFF_XS   51328                 // 3*16*72 = 3456
#define TOT_HALVES 54784
#define SMEM_MLP_BYTES (TOT_HALVES * 2 + 384 * 4)   // +biases (fp32) = 111104 B

__global__ __launch_bounds__(256)
void mlp_mma_kernel(const float* __restrict__ b1, const float* __restrict__ b2,
                    const float* __restrict__ bp2, float* __restrict__ out) {
    extern __shared__ __half sh[];
    __half* W1s = sh + OFF_W1;
    __half* W2s = sh + OFF_W2;
    __half* P1s = sh + OFF_P1;
    __half* Tsh = sh + OFF_TS;
    __half* hS  = sh + OFF_HS;
    __half* Xs  = sh + OFF_XS;
    float*  bF  = (float*)(sh + TOT_HALVES);
    float* b1s  = bF;          // 128
    float* b2s  = bF + 128;    // 64
    float* bes  = bF + 192;    // 128
    float* bp2s = bF + 320;    // 64

    int tid  = threadIdx.x;
    int w    = tid >> 5;
    int lane = tid & 31;
    int g    = lane >> 2;
    int tig  = lane & 3;
    int row0 = blockIdx.x * 16;

    // ---- stage ALL operands (one burst, one sync) ----
    {
        const uint4* s1 = (const uint4*)g_W1t;      // 128 rows x 8 uint4
        for (int i = tid; i < 1024; i += 256) {
            int r = i >> 3, q = i & 7;
            ((uint4*)&W1s[r * W1_STRIDE])[q] = s1[i];
        }
        const uint4* s2 = (const uint4*)g_W2t;      // 64 rows x 16 uint4
        for (int i = tid; i < 1024; i += 256) {
            int r = i >> 4, q = i & 15;
            ((uint4*)&W2s[r * W2_STRIDE])[q] = s2[i];
        }
        const uint4* s3 = (const uint4*)g_P1t;      // 128 rows x 24 uint4
        for (int i = tid; i < 3072; i += 256) {
            int r = i / 24, q = i - r * 24;
            ((uint4*)&P1s[r * P1_STRIDE])[q] = s3[i];
        }
        // X tiles: 3 scales x 16 rows x 8 uint4
        for (int i = tid; i < 384; i += 256) {
            int r = i >> 3, q = i & 7;              // r = scale*16 + lr
            int scale = r >> 4, lr = r & 15;
            const uint4* src = (const uint4*)(g_pooledh
                               + ((size_t)scale * NROI + row0 + lr) * 64);
            ((uint4*)&Xs[r * HS_STRIDE])[q] = src[q];
        }
        if (tid < 128) { b1s[tid] = b1[tid]; bes[tid] = g_bp1eff[tid]; }
        if (tid < 64)  { b2s[tid] = b2[tid]; bp2s[tid] = bp2[tid]; }
    }
    __syncthreads();

    // ---- per-scale heads (double-buffered Tsh; 1 sync per scale) ----
    for (int scale = 0; scale < 3; scale++) {
        __half* Tbuf = Tsh + (scale & 1) * 16 * TS_STRIDE;

        // phase A: T = relu(X@W1 + b1)  [16x128]; warp w covers ntiles 2w,2w+1
        float c[2][4];
        #pragma unroll
        for (int j = 0; j < 2; j++)
            #pragma unroll
            for (int q = 0; q < 4; q++) c[j][q] = 0.f;
        #pragma unroll
        for (int k0 = 0; k0 < 64; k0 += 16) {
            const __half* ar = Xs + (scale * 16 + g) * HS_STRIDE + k0 + 2 * tig;
            unsigned a0 = *(const unsigned*)ar;
            unsigned a1 = *(const unsigned*)(ar + 8 * HS_STRIDE);
            unsigned a2 = *(const unsigned*)(ar + 8);
            unsigned a3 = *(const unsigned*)(ar + 8 * HS_STRIDE + 8);
            #pragma unroll
            for (int j = 0; j < 2; j++) {
                const __half* bp = W1s + (w * 16 + j * 8 + g) * W1_STRIDE + k0 + 2 * tig;
                unsigned b0 = *(const unsigned*)bp;
                unsigned b1r = *(const unsigned*)(bp + 8);
                mma_f16(c[j], a0, a1, a2, a3, b0, b1r);
            }
        }
        #pragma unroll
        for (int j = 0; j < 2; j++) {
            int col = w * 16 + j * 8 + 2 * tig;
            float2 bb = *(const float2*)&b1s[col];
            __half2 lo = __floats2half2_rn(fmaxf(c[j][0] + bb.x, 0.f),
                                           fmaxf(c[j][1] + bb.y, 0.f));
            __half2 hi = __floats2half2_rn(fmaxf(c[j][2] + bb.x, 0.f),
                                           fmaxf(c[j][3] + bb.y, 0.f));
            *(__half2*)&Tbuf[g * TS_STRIDE + col] = lo;
            *(__half2*)&Tbuf[(g + 8) * TS_STRIDE + col] = hi;
        }
        __syncthreads();   // Tbuf complete for phase B

        // phase B: h = relu(T@W2 + b2)  [16x64]; warp w covers ntile w
        float d[4];
        #pragma unroll
        for (int q = 0; q < 4; q++) d[q] = 0.f;
        #pragma unroll
        for (int k0 = 0; k0 < 128; k0 += 16) {
            const __half* ar = &Tbuf[g * TS_STRIDE + k0 + 2 * tig];
            unsigned a0 = *(const unsigned*)ar;
            unsigned a1 = *(const unsigned*)(ar + 8 * TS_STRIDE);
            unsigned a2 = *(const unsigned*)(ar + 8);
            unsigned a3 = *(const unsigned*)(ar + 8 * TS_STRIDE + 8);
            const __half* bp = W2s + (w * 8 + g) * W2_STRIDE + k0 + 2 * tig;
            unsigned b0 = *(const unsigned*)bp;
            unsigned b1r = *(const unsigned*)(bp + 8);
            mma_f16(d, a0, a1, a2, a3, b0, b1r);
        }
        {
            int col = w * 8 + 2 * tig;
            float2 bb = *(const float2*)&b2s[col];
            __half2 lo = __floats2half2_rn(fmaxf(d[0] + bb.x, 0.f),
                                           fmaxf(d[1] + bb.y, 0.f));
            __half2 hi = __floats2half2_rn(fmaxf(d[2] + bb.x, 0.f),
                                           fmaxf(d[3] + bb.y, 0.f));
            __half* hdst = hS + scale * 16 * HS_STRIDE;
            *(__half2*)&hdst[g * HS_STRIDE + col] = lo;
            *(__half2*)&hdst[(g + 8) * HS_STRIDE + col] = hi;
        }
        // no sync: next phase A writes the OTHER Tsh buffer; hS synced before final1
    }
    __syncthreads();   // all hS complete

    // ---- final layer 1: T = relu(cat(h)@P1 + bp1eff)  [16x128], K=192 ----
    __half* Tf = Tsh + 16 * TS_STRIDE;   // buffer 1 (safe: last read pre-sync)
    float c[2][4];
    #pragma unroll
    for (int j = 0; j < 2; j++)
        #pragma unroll
        for (int q = 0; q < 4; q++) c[j][q] = 0.f;
    #pragma unroll
    for (int k0 = 0; k0 < 192; k0 += 16) {
        int chunk = k0 >> 6;
        int kin = k0 & 63;
        const __half* ar = hS + chunk * 16 * HS_STRIDE + g * HS_STRIDE + kin + 2 * tig;
        unsigned a0 = *(const unsigned*)ar;
        unsigned a1 = *(const unsigned*)(ar + 8 * HS_STRIDE);
        unsigned a2 = *(const unsigned*)(ar + 8);
        unsigned a3 = *(const unsigned*)(ar + 8 * HS_STRIDE + 8);
        #pragma unroll
        for (int j = 0; j < 2; j++) {
            const __half* bp = P1s + (w * 16 + j * 8 + g) * P1_STRIDE + k0 + 2 * tig;
            unsigned b0 = *(const unsigned*)bp;
            unsigned b1r = *(const unsigned*)(bp + 8);
            mma_f16(c[j], a0, a1, a2, a3, b0, b1r);
        }
    }
    #pragma unroll
    for (int j = 0; j < 2; j++) {
        int col = w * 16 + j * 8 + 2 * tig;
        float2 bb = *(const float2*)&bes[col];
        __half2 lo = __floats2half2_rn(fmaxf(c[j][0] + bb.x, 0.f),
                                       fmaxf(c[j][1] + bb.y, 0.f));
        __half2 hi = __floats2half2_rn(fmaxf(c[j][2] + bb.x, 0.f),
                                       fmaxf(c[j][3] + bb.y, 0.f));
        *(__half2*)&Tf[g * TS_STRIDE + col] = lo;
        *(__half2*)&Tf[(g + 8) * TS_STRIDE + col] = hi;
    }

    // stage P2 into W1s region (last W1 read was 2 syncs ago) while Tf completes
    {
        const uint4* s4 = (const uint4*)g_P2t;      // 64 rows x 16 uint4
        for (int i = tid; i < 1024; i += 256) {
            int r = i >> 4, q = i & 15;
            ((uint4*)&W1s[r * P2_STRIDE])[q] = s4[i];
        }
    }
    __syncthreads();   // Tf + P2s ready

    // ---- final layer 2: out = relu(T@P2 + bp2)  [16x64] fp32 ----
    float d[4];
    #pragma unroll
    for (int q = 0; q < 4; q++) d[q] = 0.f;
    #pragma unroll
    for (int k0 = 0; k0 < 128; k0 += 16) {
        const __half* ar = &Tf[g * TS_STRIDE + k0 + 2 * tig];
        unsigned a0 = *(const unsigned*)ar;
        unsigned a1 = *(const unsigned*)(ar + 8 * TS_STRIDE);
        unsigned a2 = *(const unsigned*)(ar + 8);
        unsigned a3 = *(const unsigned*)(ar + 8 * TS_STRIDE + 8);
        const __half* bp = W1s + (w * 8 + g) * P2_STRIDE + k0 + 2 * tig;
        unsigned b0 = *(const unsigned*)bp;
        unsigned b1r = *(const unsigned*)(bp + 8);
        mma_f16(d, a0, a1, a2, a3, b0, b1r);
    }
    {
        int col = w * 8 + 2 * tig;
        float2 bb = *(const float2*)&bp2s[col];
        int r_lo = row0 + g;
        float2 lo, hi;
        lo.x = fmaxf(d[0] + bb.x, 0.f);
        lo.y = fmaxf(d[1] + bb.y, 0.f);
        hi.x = fmaxf(d[2] + bb.x, 0.f);
        hi.y = fmaxf(d[3] + bb.y, 0.f);
        *(float2*)&out[(size_t)r_lo * 64 + col] = lo;
        *(float2*)&out[(size_t)(r_lo + 8) * 64 + col] = hi;
    }
}

// ---------------- launch ----------------
extern "C" void kernel_launch(void* const* d_in, const int* in_sizes, int n_in,
                              void* d_out, int out_size) {
    const float* fm    = (const float*)d_in[0];
    const float* boxes = (const float*)d_in[1];
    const float* W1    = (const float*)d_in[2];
    const float* b1    = (const float*)d_in[3];
    const float* W2    = (const float*)d_in[4];
    const float* b2    = (const float*)d_in[5];
    const float* P1    = (const float*)d_in[6];
    const float* bp1   = (const float*)d_in[7];
    const float* P2    = (const float*)d_in[8];
    const float* bp2   = (const float*)d_in[9];
    float* out = (float*)d_out;

    cudaFuncSetAttribute(mlp_mma_kernel, cudaFuncAttributeMaxDynamicSharedMemorySize,
                         SMEM_MLP_BYTES);

    transpose_prep_kernel<<<NBT + 48, 256>>>(fm, W1, W2, P1, P2);
    head_const_kernel<<<1, 128>>>(W1, b1, W2, b2, P1, bp1);

    const int PB = (3 * NROI) / 8;  // 1500 blocks
    pool_all_kernel<<<PB, 256>>>(boxes);

    mlp_mma_kernel<<<NROI / 16, 256, SMEM_MLP_BYTES>>>(b1, b2, bp2, out);
}

// round 16
// speedup vs baseline: 2.1145x; 1.1209x over previous
#include <cuda_runtime.h>
#include <cuda_fp16.h>
#include <cstdint>

#define NROI 4000
#define CCH  64
#define FH   240
#define FW   240
#define NPIX (FH*FW)
#define NBT  (NPIX / 64)   // 900 transpose blocks
#define PB   ((3 * NROI) / 8)  // 1500 pool blocks

// ---------------- scratch (no allocations allowed) ----------------
__device__ __align__(16) __half2 g_fmTh[NPIX * 32];   // HWC fp16 fm (7.4 MB)
__device__ __align__(16) __half  g_pooledh[3 * NROI * CCH]; // pooled feats fp16
__device__ float g_gpart[NBT * CCH];       // per-block channel partial sums
__device__ float g_bp1eff[128];            // bp1 + head(g) @ P1[192:256]
// fp16 transposed weights, [n][k] layout (B col-major fragments)
__device__ __align__(16) __half g_W1t[128 * 64];
__device__ __align__(16) __half g_W2t[64 * 128];
__device__ __align__(16) __half g_P1t[128 * 192];
__device__ __align__(16) __half g_P2t[64 * 128];

// ---------------- mma.sync m16n8k16 f16 -> f32 ----------------
__device__ __forceinline__ void mma_f16(float* c,
                                        unsigned a0, unsigned a1, unsigned a2, unsigned a3,
                                        unsigned b0, unsigned b1) {
    asm volatile(
        "mma.sync.aligned.m16n8k16.row.col.f32.f16.f16.f32 "
        "{%0,%1,%2,%3}, {%4,%5,%6,%7}, {%8,%9}, {%0,%1,%2,%3};\n"
        : "+f"(c[0]), "+f"(c[1]), "+f"(c[2]), "+f"(c[3])
        : "r"(a0), "r"(a1), "r"(a2), "r"(a3), "r"(b0), "r"(b1));
}

// ---------------- 1) transpose + gmean partials + weight prep (fused) ----------------
__global__ void transpose_prep_kernel(const float* __restrict__ fm,
                                      const float* __restrict__ W1, const float* __restrict__ W2,
                                      const float* __restrict__ P1, const float* __restrict__ P2) {
    int b = blockIdx.x;
    int tid = threadIdx.x;
    if (b >= NBT) {
        // weight conversion: 48 blocks x 256 thr x 4 elems = 49152
        int base = (b - NBT) * 1024;
        #pragma unroll
        for (int q = 0; q < 4; q++) {
            int idx = base + q * 256 + tid;
            if (idx < 8192) {                       // W1t[128][64]
                int n = idx >> 6, k = idx & 63;
                g_W1t[idx] = __float2half(W1[k * 128 + n]);
            } else if (idx < 16384) {               // W2t[64][128]
                int i = idx - 8192;
                int n = i >> 7, k = i & 127;
                g_W2t[i] = __float2half(W2[k * 64 + n]);
            } else if (idx < 40960) {               // P1t[128][192]
                int i = idx - 16384;
                int n = i / 192, k = i - n * 192;
                g_P1t[i] = __float2half(P1[k * 128 + n]);
            } else if (idx < 49152) {               // P2t[64][128]
                int i = idx - 40960;
                int n = i >> 7, k = i & 127;
                g_P2t[i] = __float2half(P2[k * 64 + n]);
            }
        }
        return;
    }
    __shared__ float tile[64][65];
    int pix0 = b * 64;
    int lane = tid & 63;
    int grp  = tid >> 6;
    #pragma unroll
    for (int c = grp; c < 64; c += 4)
        tile[c][lane] = fm[c * NPIX + pix0 + lane];
    __syncthreads();
    int c2 = tid & 31;
    int pg = tid >> 5;
    #pragma unroll
    for (int p = pg; p < 64; p += 8)
        g_fmTh[(pix0 + p) * 32 + c2] =
            __floats2half2_rn(tile[2 * c2][p], tile[2 * c2 + 1][p]);
    if (tid < 64) {
        float s = 0.f;
        #pragma unroll 16
        for (int p = 0; p < 64; p++) s += tile[tid][p];
        g_gpart[b * 64 + tid] = s;
    }
}

// ---------------- 2) pooling (+ head_const in the extra block) ----------------
template<int S>
__device__ __forceinline__ void pool_roi_v(int n, int lane,
                                           const float* __restrict__ boxes,
                                           __half* __restrict__ outb) {
    constexpr int SS = S * S;
    int sub = lane >> 3;
    int cl  = lane & 7;

    float bx1 = __ldg(&boxes[n * 4 + 0]);
    float by1 = __ldg(&boxes[n * 4 + 1]);
    float bx2 = __ldg(&boxes[n * 4 + 2]);
    float by2 = __ldg(&boxes[n * 4 + 3]);
    float nx1 = bx1 * (2.0f / 960.0f) - 1.0f;
    float ny1 = by1 * (2.0f / 960.0f) - 1.0f;
    float nx2 = bx2 * (2.0f / 960.0f) - 1.0f;
    float ny2 = by2 * (2.0f / 960.0f) - 1.0f;
    float cx = (nx1 + nx2) * 0.5f;
    float cy = (ny1 + ny2) * 0.5f;
    float w  = fmaxf(nx2 - nx1, 1e-6f);
    float h  = fmaxf(ny2 - ny1, 1e-6f);
    float stepx = w * (120.0f / (float)S);
    float stepy = h * (120.0f / (float)S);
    float ixb = fmaf(w * 60.0f, (1.0f / (float)S - 1.0f), fmaf(cx, 120.0f, 119.5f));
    float iyb = fmaf(h * 60.0f, (1.0f / (float)S - 1.0f), fmaf(cy, 120.0f, 119.5f));

    float acc[8];
    #pragma unroll
    for (int k = 0; k < 8; k++) acc[k] = 0.f;

    const uint4* fm4 = (const uint4*)g_fmTh;

    #pragma unroll 2
    for (int base = 0; base < SS; base += 4) {
        int samp = base + sub;
        bool alive = (samp < SS);
        int sc = alive ? samp : 0;
        int i = sc / S;
        int j = sc - i * S;
        float ix = fmaf((float)j, stepx, ixb);
        float iy = fmaf((float)i, stepy, iyb);
        float x0f = floorf(ix), y0f = floorf(iy);
        float dx = ix - x0f, dy = iy - y0f;
        int x0 = (int)x0f, y0 = (int)y0f;
        int x1 = x0 + 1,   y1 = y0 + 1;
        float wx0 = ((unsigned)x0 < FW) ? (1.f - dx) : 0.f;
        float wx1 = ((unsigned)x1 < FW) ? dx : 0.f;
        float wy0 = (alive && (unsigned)y0 < FH) ? (1.f - dy) : 0.f;
        float wy1 = (alive && (unsigned)y1 < FH) ? dy : 0.f;
        int xc0 = max(0, min(x0, FW - 1));
        int xc1 = max(0, min(x1, FW - 1));
        int yc0 = max(0, min(y0, FH - 1));
        int yc1 = max(0, min(y1, FH - 1));
        int r0 = yc0 * FW, r1 = yc1 * FW;
        uint4 q00 = __ldg(&fm4[(r0 + xc0) * 8 + cl]);
        uint4 q01 = __ldg(&fm4[(r0 + xc1) * 8 + cl]);
        uint4 q10 = __ldg(&fm4[(r1 + xc0) * 8 + cl]);
        uint4 q11 = __ldg(&fm4[(r1 + xc1) * 8 + cl]);
        __half2 h00 = __float2half2_rn(wy0 * wx0);
        __half2 h01 = __float2half2_rn(wy0 * wx1);
        __half2 h10 = __float2half2_rn(wy1 * wx0);
        __half2 h11 = __float2half2_rn(wy1 * wx1);
        const __half2* f00 = (const __half2*)&q00;
        const __half2* f01 = (const __half2*)&q01;
        const __half2* f10 = (const __half2*)&q10;
        const __half2* f11 = (const __half2*)&q11;
        #pragma unroll
        for (int k = 0; k < 4; k++) {
            __half2 s = __hmul2(h00, f00[k]);
            s = __hfma2(h01, f01[k], s);
            s = __hfma2(h10, f10[k], s);
            s = __hfma2(h11, f11[k], s);
            float2 fs = __half22float2(s);
            acc[2 * k]     += fs.x;
            acc[2 * k + 1] += fs.y;
        }
    }

    #pragma unroll
    for (int k = 0; k < 8; k++) {
        acc[k] += __shfl_down_sync(0xffffffffu, acc[k], 16);
        acc[k] += __shfl_down_sync(0xffffffffu, acc[k], 8);
    }
    if (sub == 0) {
        const float inv = 1.0f / (float)SS;
        __half2 p[4];
        #pragma unroll
        for (int k = 0; k < 4; k++)
            p[k] = __floats2half2_rn(acc[2 * k] * inv, acc[2 * k + 1] * inv);
        *(uint4*)&outb[(size_t)n * 64 + cl * 8] = *(uint4*)p;
    }
}

__global__ void pool_all_kernel(const float* __restrict__ boxes,
                                const float* __restrict__ W1, const float* __restrict__ b1,
                                const float* __restrict__ W2, const float* __restrict__ b2,
                                const float* __restrict__ P1, const float* __restrict__ bp1) {
    if (blockIdx.x == PB) {
        // ---- head_const: gmean reduce + fold head(g) into bp1 (256 threads, <128 active) ----
        __shared__ float gs[64];
        __shared__ float part[2][64];
        __shared__ float t[128];
        __shared__ float hg[64];
        int tid = threadIdx.x;
        if (tid < 128) {
            int ch = tid & 63;
            int half = tid >> 6;
            int b0 = half * (NBT / 2);
            int b1e = b0 + (NBT / 2);
            float s = 0.f;
            for (int b = b0; b < b1e; b++) s += g_gpart[b * 64 + ch];
            part[half][ch] = s;
        }
        __syncthreads();
        if (tid < 64)
            gs[tid] = (part[0][tid] + part[1][tid]) * (1.0f / (float)NPIX);
        __syncthreads();
        if (tid < 128) {
            float a = b1[tid];
            #pragma unroll 8
            for (int c = 0; c < 64; c++) a = fmaf(gs[c], W1[c * 128 + tid], a);
            t[tid] = fmaxf(a, 0.f);
        }
        __syncthreads();
        if (tid < 64) {
            float a2 = b2[tid];
            #pragma unroll 8
            for (int k = 0; k < 128; k++) a2 = fmaf(t[k], W2[k * 64 + tid], a2);
            hg[tid] = fmaxf(a2, 0.f);
        }
        __syncthreads();
        if (tid < 128) {
            float be = bp1[tid];
            #pragma unroll 8
            for (int c = 0; c < 64; c++) be = fmaf(hg[c], P1[(192 + c) * 128 + tid], be);
            g_bp1eff[tid] = be;
        }
        return;
    }
    int tid  = threadIdx.x;
    int lane = tid & 31;
    int warp = tid >> 5;
    int task = blockIdx.x * 8 + warp;   // LPT: S=11 first, S=3 last
    if (task < NROI) {
        pool_roi_v<11>(task, lane, boxes, g_pooledh + (size_t)2 * NROI * CCH);
    } else if (task < 2 * NROI) {
        pool_roi_v<7>(task - NROI, lane, boxes, g_pooledh + (size_t)NROI * CCH);
    } else {
        pool_roi_v<3>(task - 2 * NROI, lane, boxes, g_pooledh);
    }
}

// ---------------- 3) fused MLP: batched scales, 4 syncs, all-smem operands ----------------
#define TS_STRIDE 136
#define HS_STRIDE 72
#define W1_STRIDE 72
#define W2_STRIDE 136
#define P1_STRIDE 200
#define P2_STRIDE 136
// smem layout (halves)
#define OFF_W1   0                     // 128*72  = 9216  (P2 reuses later)
#define OFF_W2   9216                  // 64*136  = 8704
#define OFF_P1   17920                 // 128*200 = 25600
#define OFF_TS   43520                 // 48*136  = 6528
#define OFF_HS   50048                 // 48*72   = 3456
#define OFF_XS   53504                 // 48*72   = 3456
#define TOT_HALVES 56960
#define SMEM_MLP_BYTES (TOT_HALVES * 2)   // 113920 B -> 2 CTAs/SM

__global__ __launch_bounds__(256)
void mlp_mma_kernel(const float* __restrict__ b1, const float* __restrict__ b2,
                    const float* __restrict__ bp2, float* __restrict__ out) {
    extern __shared__ __half sh[];
    __half* W1s = sh + OFF_W1;
    __half* W2s = sh + OFF_W2;
    __half* P1s = sh + OFF_P1;
    __half* Tsh = sh + OFF_TS;
    __half* hS  = sh + OFF_HS;
    __half* Xs  = sh + OFF_XS;

    int tid  = threadIdx.x;
    int w    = tid >> 5;
    int lane = tid & 31;
    int g    = lane >> 2;
    int tig  = lane & 3;
    int row0 = blockIdx.x * 16;

    // ---- stage ALL operands (one burst, one sync) ----
    {
        const uint4* s1 = (const uint4*)g_W1t;      // 128 rows x 8 uint4
        for (int i = tid; i < 1024; i += 256) {
            int r = i >> 3, q = i & 7;
            ((uint4*)&W1s[r * W1_STRIDE])[q] = s1[i];
        }
        const uint4* s2 = (const uint4*)g_W2t;      // 64 rows x 16 uint4
        for (int i = tid; i < 1024; i += 256) {
            int r = i >> 4, q = i & 15;
            ((uint4*)&W2s[r * W2_STRIDE])[q] = s2[i];
        }
        const uint4* s3 = (const uint4*)g_P1t;      // 128 rows x 24 uint4
        for (int i = tid; i < 3072; i += 256) {
            int r = i / 24, q = i - r * 24;
            ((uint4*)&P1s[r * P1_STRIDE])[q] = s3[i];
        }
        // X tiles: 3 scales x 16 rows x 8 uint4 (row r = scale*16 + lr)
        for (int i = tid; i < 384; i += 256) {
            int r = i >> 3, q = i & 7;
            int scale = r >> 4, lr = r & 15;
            const uint4* src = (const uint4*)(g_pooledh
                               + ((size_t)scale * NROI + row0 + lr) * 64);
            ((uint4*)&Xs[r * HS_STRIDE])[q] = src[q];
        }
    }
    __syncthreads();

    // ---- phase A (all scales): Ts[48][128] = relu(X@W1 + b1) ----
    // warp w: ntiles 2w,2w+1 x mtiles 0..2 -> 6 c-tiles, 24 mmas
    {
        float c[3][2][4];
        #pragma unroll
        for (int mt = 0; mt < 3; mt++)
            #pragma unroll
            for (int j = 0; j < 2; j++)
                #pragma unroll
                for (int q = 0; q < 4; q++) c[mt][j][q] = 0.f;
        #pragma unroll
        for (int k0 = 0; k0 < 64; k0 += 16) {
            unsigned a[3][4];
            #pragma unroll
            for (int mt = 0; mt < 3; mt++) {
                const __half* ar = Xs + (mt * 16 + g) * HS_STRIDE + k0 + 2 * tig;
                a[mt][0] = *(const unsigned*)ar;
                a[mt][1] = *(const unsigned*)(ar + 8 * HS_STRIDE);
                a[mt][2] = *(const unsigned*)(ar + 8);
                a[mt][3] = *(const unsigned*)(ar + 8 * HS_STRIDE + 8);
            }
            #pragma unroll
            for (int j = 0; j < 2; j++) {
                const __half* bp = W1s + (w * 16 + j * 8 + g) * W1_STRIDE + k0 + 2 * tig;
                unsigned b0 = *(const unsigned*)bp;
                unsigned b1r = *(const unsigned*)(bp + 8);
                #pragma unroll
                for (int mt = 0; mt < 3; mt++)
                    mma_f16(c[mt][j], a[mt][0], a[mt][1], a[mt][2], a[mt][3], b0, b1r);
            }
        }
        #pragma unroll
        for (int j = 0; j < 2; j++) {
            int col = w * 16 + j * 8 + 2 * tig;
            float2 bb = *(const float2*)&b1[col];
            #pragma unroll
            for (int mt = 0; mt < 3; mt++) {
                __half2 lo = __floats2half2_rn(fmaxf(c[mt][j][0] + bb.x, 0.f),
                                               fmaxf(c[mt][j][1] + bb.y, 0.f));
                __half2 hi = __floats2half2_rn(fmaxf(c[mt][j][2] + bb.x, 0.f),
                                               fmaxf(c[mt][j][3] + bb.y, 0.f));
                *(__half2*)&Tsh[(mt * 16 + g) * TS_STRIDE + col] = lo;
                *(__half2*)&Tsh[(mt * 16 + g + 8) * TS_STRIDE + col] = hi;
            }
        }
    }
    __syncthreads();

    // ---- phase B (all scales): h[48][64] = relu(Ts@W2 + b2) ----
    // warp w: ntile w x mtiles 0..2 -> 3 tiles, 24 mmas
    {
        float d[3][4];
        #pragma unroll
        for (int mt = 0; mt < 3; mt++)
            #pragma unroll
            for (int q = 0; q < 4; q++) d[mt][q] = 0.f;
        #pragma unroll
        for (int k0 = 0; k0 < 128; k0 += 16) {
            const __half* bp = W2s + (w * 8 + g) * W2_STRIDE + k0 + 2 * tig;
            unsigned b0 = *(const unsigned*)bp;
            unsigned b1r = *(const unsigned*)(bp + 8);
            #pragma unroll
            for (int mt = 0; mt < 3; mt++) {
                const __half* ar = &Tsh[(mt * 16 + g) * TS_STRIDE + k0 + 2 * tig];
                unsigned a0 = *(const unsigned*)ar;
                unsigned a1 = *(const unsigned*)(ar + 8 * TS_STRIDE);
                unsigned a2 = *(const unsigned*)(ar + 8);
                unsigned a3 = *(const unsigned*)(ar + 8 * TS_STRIDE + 8);
                mma_f16(d[mt], a0, a1, a2, a3, b0, b1r);
            }
        }
        int col = w * 8 + 2 * tig;
        float2 bb = *(const float2*)&b2[col];
        #pragma unroll
        for (int mt = 0; mt < 3; mt++) {
            __half2 lo = __floats2half2_rn(fmaxf(d[mt][0] + bb.x, 0.f),
                                           fmaxf(d[mt][1] + bb.y, 0.f));
            __half2 hi = __floats2half2_rn(fmaxf(d[mt][2] + bb.x, 0.f),
                                           fmaxf(d[mt][3] + bb.y, 0.f));
            *(__half2*)&hS[(mt * 16 + g) * HS_STRIDE + col] = lo;
            *(__half2*)&hS[(mt * 16 + g + 8) * HS_STRIDE + col] = hi;
        }
    }
    __syncthreads();

    // ---- final layer 1: Tf[16][128] = relu(cat(h)@P1 + bp1eff), K=192 ----
    // hS rows ARE the concat chunks. warp w: ntiles 2w,2w+1.
    {
        float c2[2][4];
        #pragma unroll
        for (int j = 0; j < 2; j++)
            #pragma unroll
            for (int q = 0; q < 4; q++) c2[j][q] = 0.f;
        #pragma unroll
        for (int k0 = 0; k0 < 192; k0 += 16) {
            int chunk = k0 >> 6;
            int kin = k0 & 63;
            const __half* ar = hS + (chunk * 16 + g) * HS_STRIDE + kin + 2 * tig;
            unsigned a0 = *(const unsigned*)ar;
            unsigned a1 = *(const unsigned*)(ar + 8 * HS_STRIDE);
            unsigned a2 = *(const unsigned*)(ar + 8);
            unsigned a3 = *(const unsigned*)(ar + 8 * HS_STRIDE + 8);
            #pragma unroll
            for (int j = 0; j < 2; j++) {
                const __half* bp = P1s + (w * 16 + j * 8 + g) * P1_STRIDE + k0 + 2 * tig;
                unsigned b0 = *(const unsigned*)bp;
                unsigned b1r = *(const unsigned*)(bp + 8);
                mma_f16(c2[j], a0, a1, a2, a3, b0, b1r);
            }
        }
        #pragma unroll
        for (int j = 0; j < 2; j++) {
            int col = w * 16 + j * 8 + 2 * tig;
            float2 bb = *(const float2*)&g_bp1eff[col];
            __half2 lo = __floats2half2_rn(fmaxf(c2[j][0] + bb.x, 0.f),
                                           fmaxf(c2[j][1] + bb.y, 0.f));
            __half2 hi = __floats2half2_rn(fmaxf(c2[j][2] + bb.x, 0.f),
                                           fmaxf(c2[j][3] + bb.y, 0.f));
            *(__half2*)&Tsh[g * TS_STRIDE + col] = lo;
            *(__half2*)&Tsh[(g + 8) * TS_STRIDE + col] = hi;
        }
    }
    // stage P2 into W1s region (W1 reads ended at phase A->B sync)
    {
        const uint4* s4 = (const uint4*)g_P2t;      // 64 rows x 16 uint4
        for (int i = tid; i < 1024; i += 256) {
            int r = i >> 4, q = i & 15;
            ((uint4*)&W1s[r * P2_STRIDE])[q] = s4[i];
        }
    }
    __syncthreads();

    // ---- final layer 2: out = relu(Tf@P2 + bp2)  [16x64] fp32 ----
    {
        float dd[4];
        #pragma unroll
        for (int q = 0; q < 4; q++) dd[q] = 0.f;
        #pragma unroll
        for (int k0 = 0; k0 < 128; k0 += 16) {
            const __half* ar = &Tsh[g * TS_STRIDE + k0 + 2 * tig];
            unsigned a0 = *(const unsigned*)ar;
            unsigned a1 = *(const unsigned*)(ar + 8 * TS_STRIDE);
            unsigned a2 = *(const unsigned*)(ar + 8);
            unsigned a3 = *(const unsigned*)(ar + 8 * TS_STRIDE + 8);
            const __half* bp = W1s + (w * 8 + g) * P2_STRIDE + k0 + 2 * tig;
            unsigned b0 = *(const unsigned*)bp;
            unsigned b1r = *(const unsigned*)(bp + 8);
            mma_f16(dd, a0, a1, a2, a3, b0, b1r);
        }
        int col = w * 8 + 2 * tig;
        float2 bb = *(const float2*)&bp2[col];
        int r_lo = row0 + g;
        float2 lo, hi;
        lo.x = fmaxf(dd[0] + bb.x, 0.f);
        lo.y = fmaxf(dd[1] + bb.y, 0.f);
        hi.x = fmaxf(dd[2] + bb.x, 0.f);
        hi.y = fmaxf(dd[3] + bb.y, 0.f);
        *(float2*)&out[(size_t)r_lo * 64 + col] = lo;
        *(float2*)&out[(size_t)(r_lo + 8) * 64 + col] = hi;
    }
}

// ---------------- launch ----------------
extern "C" void kernel_launch(void* const* d_in, const int* in_sizes, int n_in,
                              void* d_out, int out_size) {
    const float* fm    = (const float*)d_in[0];
    const float* boxes = (const float*)d_in[1];
    const float* W1    = (const float*)d_in[2];
    const float* b1    = (const float*)d_in[3];
    const float* W2    = (const float*)d_in[4];
    const float* b2    = (const float*)d_in[5];
    const float* P1    = (const float*)d_in[6];
    const float* bp1   = (const float*)d_in[7];
    const float* P2    = (const float*)d_in[8];
    const float* bp2   = (const float*)d_in[9];
    float* out = (float*)d_out;

    cudaFuncSetAttribute(mlp_mma_kernel, cudaFuncAttributeMaxDynamicSharedMemorySize,
                         SMEM_MLP_BYTES);

    transpose_prep_kernel<<<NBT + 48, 256>>>(fm, W1, W2, P1, P2);
    pool_all_kernel<<<PB + 1, 256>>>(boxes, W1, b1, W2, b2, P1, bp1);
    mlp_mma_kernel<<<NROI / 16, 256, SMEM_MLP_BYTES>>>(b1, b2, bp2, out);
}

// round 17
// speedup vs baseline: 2.1392x; 1.0117x over previous
#include <cuda_runtime.h>
#include <cuda_fp16.h>
#include <cstdint>

#define NROI 4000
#define CCH  64
#define FH   240
#define FW   240
#define NPIX (FH*FW)
#define NBT  (NPIX / 64)   // 900 transpose blocks
#define PB   ((3 * NROI) / 8)  // 1500 pool blocks

// ---------------- scratch (no allocations allowed) ----------------
__device__ __align__(16) __half2 g_fmTh[NPIX * 32];   // HWC fp16 fm (7.4 MB)
__device__ __align__(16) __half  g_pooledh[3 * NROI * CCH]; // pooled feats fp16
__device__ float g_gpart[NBT * CCH];       // per-block channel partial sums
__device__ float g_bp1eff[128];            // bp1 + head(g) @ P1[192:256]
// fp16 transposed weights, [n][k] layout (B col-major fragments)
__device__ __align__(16) __half g_W1t[128 * 64];
__device__ __align__(16) __half g_W2t[64 * 128];
__device__ __align__(16) __half g_P1t[128 * 192];
__device__ __align__(16) __half g_P2t[64 * 128];

// ---------------- mma.sync m16n8k16 f16 -> f32 ----------------
__device__ __forceinline__ void mma_f16(float* c,
                                        unsigned a0, unsigned a1, unsigned a2, unsigned a3,
                                        unsigned b0, unsigned b1) {
    asm volatile(
        "mma.sync.aligned.m16n8k16.row.col.f32.f16.f16.f32 "
        "{%0,%1,%2,%3}, {%4,%5,%6,%7}, {%8,%9}, {%0,%1,%2,%3};\n"
        : "+f"(c[0]), "+f"(c[1]), "+f"(c[2]), "+f"(c[3])
        : "r"(a0), "r"(a1), "r"(a2), "r"(a3), "r"(b0), "r"(b1));
}

// ---------------- 1) transpose + gmean partials + weight prep (fused) ----------------
__global__ void transpose_prep_kernel(const float* __restrict__ fm,
                                      const float* __restrict__ W1, const float* __restrict__ W2,
                                      const float* __restrict__ P1, const float* __restrict__ P2) {
    int b = blockIdx.x;
    int tid = threadIdx.x;
    if (b >= NBT) {
        // weight conversion: 48 blocks x 256 thr x 4 elems = 49152
        int base = (b - NBT) * 1024;
        #pragma unroll
        for (int q = 0; q < 4; q++) {
            int idx = base + q * 256 + tid;
            if (idx < 8192) {                       // W1t[128][64]
                int n = idx >> 6, k = idx & 63;
                g_W1t[idx] = __float2half(W1[k * 128 + n]);
            } else if (idx < 16384) {               // W2t[64][128]
                int i = idx - 8192;
                int n = i >> 7, k = i & 127;
                g_W2t[i] = __float2half(W2[k * 64 + n]);
            } else if (idx < 40960) {               // P1t[128][192]
                int i = idx - 16384;
                int n = i / 192, k = i - n * 192;
                g_P1t[i] = __float2half(P1[k * 128 + n]);
            } else if (idx < 49152) {               // P2t[64][128]
                int i = idx - 40960;
                int n = i >> 7, k = i & 127;
                g_P2t[i] = __float2half(P2[k * 64 + n]);
            }
        }
        return;
    }
    __shared__ float tile[64][65];
    int pix0 = b * 64;
    int lane = tid & 63;
    int grp  = tid >> 6;
    #pragma unroll
    for (int c = grp; c < 64; c += 4)
        tile[c][lane] = fm[c * NPIX + pix0 + lane];
    __syncthreads();
    int c2 = tid & 31;
    int pg = tid >> 5;
    #pragma unroll
    for (int p = pg; p < 64; p += 8)
        g_fmTh[(pix0 + p) * 32 + c2] =
            __floats2half2_rn(tile[2 * c2][p], tile[2 * c2 + 1][p]);
    if (tid < 64) {
        float s = 0.f;
        #pragma unroll 16
        for (int p = 0; p < 64; p++) s += tile[tid][p];
        g_gpart[b * 64 + tid] = s;
    }
}

// ---------------- 2) pooling (+ head_const in the extra block) ----------------
template<int S>
__device__ __forceinline__ void pool_roi_v(int n, int lane,
                                           const float* __restrict__ boxes,
                                           __half* __restrict__ outb) {
    constexpr int SS = S * S;
    int sub = lane >> 3;
    int cl  = lane & 7;

    float4 bx = __ldg((const float4*)&boxes[n * 4]);
    float nx1 = bx.x * (2.0f / 960.0f) - 1.0f;
    float ny1 = bx.y * (2.0f / 960.0f) - 1.0f;
    float nx2 = bx.z * (2.0f / 960.0f) - 1.0f;
    float ny2 = bx.w * (2.0f / 960.0f) - 1.0f;
    float cx = (nx1 + nx2) * 0.5f;
    float cy = (ny1 + ny2) * 0.5f;
    float w  = fmaxf(nx2 - nx1, 1e-6f);
    float h  = fmaxf(ny2 - ny1, 1e-6f);
    float stepx = w * (120.0f / (float)S);
    float stepy = h * (120.0f / (float)S);
    float ixb = fmaf(w * 60.0f, (1.0f / (float)S - 1.0f), fmaf(cx, 120.0f, 119.5f));
    float iyb = fmaf(h * 60.0f, (1.0f / (float)S - 1.0f), fmaf(cy, 120.0f, 119.5f));

    float acc[8];
    #pragma unroll
    for (int k = 0; k < 8; k++) acc[k] = 0.f;

    const char* fmb = (const char*)g_fmTh + cl * 16;

    #pragma unroll 2
    for (int base = 0; base < SS; base += 4) {
        int samp = base + sub;
        bool alive = (samp < SS);
        int sc = alive ? samp : 0;
        int i = sc / S;          // const-divide -> mul/shift
        int j = sc - i * S;
        float ix = fmaf((float)j, stepx, ixb);
        float iy = fmaf((float)i, stepy, iyb);
        float x0f = floorf(ix), y0f = floorf(iy);
        float dx = ix - x0f, dy = iy - y0f;
        int x0 = (int)x0f, y0 = (int)y0f;
        // guaranteed: x0,y0 in [-1, 239]
        float wx0 = (x0 >= 0)  ? (1.f - dx) : 0.f;
        float wx1 = (x0 <= 238) ? dx : 0.f;
        float wy0 = (alive && y0 >= 0)  ? (1.f - dy) : 0.f;
        float wy1 = (alive && y0 <= 238) ? dy : 0.f;
        int xc0 = max(x0, 0);
        int xc1 = min(x0 + 1, FW - 1);
        int yc0 = max(y0, 0);
        int yc1 = min(y0 + 1, FH - 1);
        int dxB = (xc1 - xc0) << 7;          // 0 or 128
        int dyB = (yc1 - yc0) * (FW * 128);  // 0 or 30720
        int off00 = (yc0 * FW + xc0) << 7;
        const char* p00 = fmb + off00;
        uint4 q00 = *(const uint4*)(p00);
        uint4 q01 = *(const uint4*)(p00 + dxB);
        uint4 q10 = *(const uint4*)(p00 + dyB);
        uint4 q11 = *(const uint4*)(p00 + dxB + dyB);
        __half2 h00 = __float2half2_rn(wy0 * wx0);
        __half2 h01 = __float2half2_rn(wy0 * wx1);
        __half2 h10 = __float2half2_rn(wy1 * wx0);
        __half2 h11 = __float2half2_rn(wy1 * wx1);
        const __half2* f00 = (const __half2*)&q00;
        const __half2* f01 = (const __half2*)&q01;
        const __half2* f10 = (const __half2*)&q10;
        const __half2* f11 = (const __half2*)&q11;
        #pragma unroll
        for (int k = 0; k < 4; k++) {
            __half2 s = __hmul2(h00, f00[k]);
            s = __hfma2(h01, f01[k], s);
            s = __hfma2(h10, f10[k], s);
            s = __hfma2(h11, f11[k], s);
            float2 fs = __half22float2(s);
            acc[2 * k]     += fs.x;
            acc[2 * k + 1] += fs.y;
        }
    }

    #pragma unroll
    for (int k = 0; k < 8; k++) {
        acc[k] += __shfl_down_sync(0xffffffffu, acc[k], 16);
        acc[k] += __shfl_down_sync(0xffffffffu, acc[k], 8);
    }
    if (sub == 0) {
        const float inv = 1.0f / (float)SS;
        __half2 p[4];
        #pragma unroll
        for (int k = 0; k < 4; k++)
            p[k] = __floats2half2_rn(acc[2 * k] * inv, acc[2 * k + 1] * inv);
        *(uint4*)&outb[(size_t)n * 64 + cl * 8] = *(uint4*)p;
    }
}

__global__ void pool_all_kernel(const float* __restrict__ boxes,
                                const float* __restrict__ W1, const float* __restrict__ b1,
                                const float* __restrict__ W2, const float* __restrict__ b2,
                                const float* __restrict__ P1, const float* __restrict__ bp1) {
    if (blockIdx.x == PB) {
        // ---- head_const: gmean reduce + fold head(g) into bp1 ----
        __shared__ float gs[64];
        __shared__ float part[2][64];
        __shared__ float t[128];
        __shared__ float hg[64];
        int tid = threadIdx.x;
        if (tid < 128) {
            int ch = tid & 63;
            int half = tid >> 6;
            int b0 = half * (NBT / 2);
            int b1e = b0 + (NBT / 2);
            float s = 0.f;
            for (int b = b0; b < b1e; b++) s += g_gpart[b * 64 + ch];
            part[half][ch] = s;
        }
        __syncthreads();
        if (tid < 64)
            gs[tid] = (part[0][tid] + part[1][tid]) * (1.0f / (float)NPIX);
        __syncthreads();
        if (tid < 128) {
            float a = b1[tid];
            #pragma unroll 8
            for (int c = 0; c < 64; c++) a = fmaf(gs[c], W1[c * 128 + tid], a);
            t[tid] = fmaxf(a, 0.f);
        }
        __syncthreads();
        if (tid < 64) {
            float a2 = b2[tid];
            #pragma unroll 8
            for (int k = 0; k < 128; k++) a2 = fmaf(t[k], W2[k * 64 + tid], a2);
            hg[tid] = fmaxf(a2, 0.f);
        }
        __syncthreads();
        if (tid < 128) {
            float be = bp1[tid];
            #pragma unroll 8
            for (int c = 0; c < 64; c++) be = fmaf(hg[c], P1[(192 + c) * 128 + tid], be);
            g_bp1eff[tid] = be;
        }
        return;
    }
    int tid  = threadIdx.x;
    int lane = tid & 31;
    int warp = tid >> 5;
    int task = blockIdx.x * 8 + warp;   // LPT: S=11 first, S=3 last
    if (task < NROI) {
        pool_roi_v<11>(task, lane, boxes, g_pooledh + (size_t)2 * NROI * CCH);
    } else if (task < 2 * NROI) {
        pool_roi_v<7>(task - NROI, lane, boxes, g_pooledh + (size_t)NROI * CCH);
    } else {
        pool_roi_v<3>(task - 2 * NROI, lane, boxes, g_pooledh);
    }
}

// ---------------- 3) fused MLP: batched scales, 4 syncs, all-smem operands ----------------
#define TS_STRIDE 136
#define HS_STRIDE 72
#define W1_STRIDE 72
#define W2_STRIDE 136
#define P1_STRIDE 200
#define P2_STRIDE 136
// smem layout (halves)
#define OFF_W1   0                     // 128*72  = 9216  (P2 reuses later)
#define OFF_W2   9216                  // 64*136  = 8704
#define OFF_P1   17920                 // 128*200 = 25600
#define OFF_TS   43520                 // 48*136  = 6528
#define OFF_HS   50048                 // 48*72   = 3456
#define OFF_XS   53504                 // 48*72   = 3456
#define TOT_HALVES 56960
#define SMEM_MLP_BYTES (TOT_HALVES * 2)   // 113920 B -> 2 CTAs/SM

__global__ __launch_bounds__(256)
void mlp_mma_kernel(const float* __restrict__ b1, const float* __restrict__ b2,
                    const float* __restrict__ bp2, float* __restrict__ out) {
    extern __shared__ __half sh[];
    __half* W1s = sh + OFF_W1;
    __half* W2s = sh + OFF_W2;
    __half* P1s = sh + OFF_P1;
    __half* Tsh = sh + OFF_TS;
    __half* hS  = sh + OFF_HS;
    __half* Xs  = sh + OFF_XS;

    int tid  = threadIdx.x;
    int w    = tid >> 5;
    int lane = tid & 31;
    int g    = lane >> 2;
    int tig  = lane & 3;
    int row0 = blockIdx.x * 16;

    // ---- stage ALL operands (one burst, one sync) ----
    {
        const uint4* s1 = (const uint4*)g_W1t;      // 128 rows x 8 uint4
        for (int i = tid; i < 1024; i += 256) {
            int r = i >> 3, q = i & 7;
            ((uint4*)&W1s[r * W1_STRIDE])[q] = s1[i];
        }
        const uint4* s2 = (const uint4*)g_W2t;      // 64 rows x 16 uint4
        for (int i = tid; i < 1024; i += 256) {
            int r = i >> 4, q = i & 15;
            ((uint4*)&W2s[r * W2_STRIDE])[q] = s2[i];
        }
        const uint4* s3 = (const uint4*)g_P1t;      // 128 rows x 24 uint4
        for (int i = tid; i < 3072; i += 256) {
            int r = i / 24, q = i - r * 24;
            ((uint4*)&P1s[r * P1_STRIDE])[q] = s3[i];
        }
        // X tiles: 3 scales x 16 rows x 8 uint4 (row r = scale*16 + lr)
        for (int i = tid; i < 384; i += 256) {
            int r = i >> 3, q = i & 7;
            int scale = r >> 4, lr = r & 15;
            const uint4* src = (const uint4*)(g_pooledh
                               + ((size_t)scale * NROI + row0 + lr) * 64);
            ((uint4*)&Xs[r * HS_STRIDE])[q] = src[q];
        }
    }
    __syncthreads();

    // ---- phase A (all scales): Ts[48][128] = relu(X@W1 + b1) ----
    {
        float c[3][2][4];
        #pragma unroll
        for (int mt = 0; mt < 3; mt++)
            #pragma unroll
            for (int j = 0; j < 2; j++)
                #pragma unroll
                for (int q = 0; q < 4; q++) c[mt][j][q] = 0.f;
        #pragma unroll
        for (int k0 = 0; k0 < 64; k0 += 16) {
            unsigned a[3][4];
            #pragma unroll
            for (int mt = 0; mt < 3; mt++) {
                const __half* ar = Xs + (mt * 16 + g) * HS_STRIDE + k0 + 2 * tig;
                a[mt][0] = *(const unsigned*)ar;
                a[mt][1] = *(const unsigned*)(ar + 8 * HS_STRIDE);
                a[mt][2] = *(const unsigned*)(ar + 8);
                a[mt][3] = *(const unsigned*)(ar + 8 * HS_STRIDE + 8);
            }
            #pragma unroll
            for (int j = 0; j < 2; j++) {
                const __half* bp = W1s + (w * 16 + j * 8 + g) * W1_STRIDE + k0 + 2 * tig;
                unsigned b0 = *(const unsigned*)bp;
                unsigned b1r = *(const unsigned*)(bp + 8);
                #pragma unroll
                for (int mt = 0; mt < 3; mt++)
                    mma_f16(c[mt][j], a[mt][0], a[mt][1], a[mt][2], a[mt][3], b0, b1r);
            }
        }
        #pragma unroll
        for (int j = 0; j < 2; j++) {
            int col = w * 16 + j * 8 + 2 * tig;
            float2 bb = *(const float2*)&b1[col];
            #pragma unroll
            for (int mt = 0; mt < 3; mt++) {
                __half2 lo = __floats2half2_rn(fmaxf(c[mt][j][0] + bb.x, 0.f),
                                               fmaxf(c[mt][j][1] + bb.y, 0.f));
                __half2 hi = __floats2half2_rn(fmaxf(c[mt][j][2] + bb.x, 0.f),
                                               fmaxf(c[mt][j][3] + bb.y, 0.f));
                *(__half2*)&Tsh[(mt * 16 + g) * TS_STRIDE + col] = lo;
                *(__half2*)&Tsh[(mt * 16 + g + 8) * TS_STRIDE + col] = hi;
            }
        }
    }
    __syncthreads();

    // ---- phase B (all scales): h[48][64] = relu(Ts@W2 + b2) ----
    {
        float d[3][4];
        #pragma unroll
        for (int mt = 0; mt < 3; mt++)
            #pragma unroll
            for (int q = 0; q < 4; q++) d[mt][q] = 0.f;
        #pragma unroll
        for (int k0 = 0; k0 < 128; k0 += 16) {
            const __half* bp = W2s + (w * 8 + g) * W2_STRIDE + k0 + 2 * tig;
            unsigned b0 = *(const unsigned*)bp;
            unsigned b1r = *(const unsigned*)(bp + 8);
            #pragma unroll
            for (int mt = 0; mt < 3; mt++) {
                const __half* ar = &Tsh[(mt * 16 + g) * TS_STRIDE + k0 + 2 * tig];
                unsigned a0 = *(const unsigned*)ar;
                unsigned a1 = *(const unsigned*)(ar + 8 * TS_STRIDE);
                unsigned a2 = *(const unsigned*)(ar + 8);
                unsigned a3 = *(const unsigned*)(ar + 8 * TS_STRIDE + 8);
                mma_f16(d[mt], a0, a1, a2, a3, b0, b1r);
            }
        }
        int col = w * 8 + 2 * tig;
        float2 bb = *(const float2*)&b2[col];
        #pragma unroll
        for (int mt = 0; mt < 3; mt++) {
            __half2 lo = __floats2half2_rn(fmaxf(d[mt][0] + bb.x, 0.f),
                                           fmaxf(d[mt][1] + bb.y, 0.f));
            __half2 hi = __floats2half2_rn(fmaxf(d[mt][2] + bb.x, 0.f),
                                           fmaxf(d[mt][3] + bb.y, 0.f));
            *(__half2*)&hS[(mt * 16 + g) * HS_STRIDE + col] = lo;
            *(__half2*)&hS[(mt * 16 + g + 8) * HS_STRIDE + col] = hi;
        }
    }
    __syncthreads();

    // ---- final layer 1: Tf[16][128] = relu(cat(h)@P1 + bp1eff), K=192 ----
    {
        float c2[2][4];
        #pragma unroll
        for (int j = 0; j < 2; j++)
            #pragma unroll
            for (int q = 0; q < 4; q++) c2[j][q] = 0.f;
        #pragma unroll
        for (int k0 = 0; k0 < 192; k0 += 16) {
            int chunk = k0 >> 6;
            int kin = k0 & 63;
            const __half* ar = hS + (chunk * 16 + g) * HS_STRIDE + kin + 2 * tig;
            unsigned a0 = *(const unsigned*)ar;
            unsigned a1 = *(const unsigned*)(ar + 8 * HS_STRIDE);
            unsigned a2 = *(const unsigned*)(ar + 8);
            unsigned a3 = *(const unsigned*)(ar + 8 * HS_STRIDE + 8);
            #pragma unroll
            for (int j = 0; j < 2; j++) {
                const __half* bp = P1s + (w * 16 + j * 8 + g) * P1_STRIDE + k0 + 2 * tig;
                unsigned b0 = *(const unsigned*)bp;
                unsigned b1r = *(const unsigned*)(bp + 8);
                mma_f16(c2[j], a0, a1, a2, a3, b0, b1r);
            }
        }
        #pragma unroll
        for (int j = 0; j < 2; j++) {
            int col = w * 16 + j * 8 + 2 * tig;
            float2 bb = *(const float2*)&g_bp1eff[col];
            __half2 lo = __floats2half2_rn(fmaxf(c2[j][0] + bb.x, 0.f),
                                           fmaxf(c2[j][1] + bb.y, 0.f));
            __half2 hi = __floats2half2_rn(fmaxf(c2[j][2] + bb.x, 0.f),
                                           fmaxf(c2[j][3] + bb.y, 0.f));
            *(__half2*)&Tsh[g * TS_STRIDE + col] = lo;
            *(__half2*)&Tsh[(g + 8) * TS_STRIDE + col] = hi;
        }
    }
    // stage P2 into W1s region (W1 reads ended at phase A->B sync)
    {
        const uint4* s4 = (const uint4*)g_P2t;      // 64 rows x 16 uint4
        for (int i = tid; i < 1024; i += 256) {
            int r = i >> 4, q = i & 15;
            ((uint4*)&W1s[r * P2_STRIDE])[q] = s4[i];
        }
    }
    __syncthreads();

    // ---- final layer 2: out = relu(Tf@P2 + bp2)  [16x64] fp32 ----
    {
        float dd[4];
        #pragma unroll
        for (int q = 0; q < 4; q++) dd[q] = 0.f;
        #pragma unroll
        for (int k0 = 0; k0 < 128; k0 += 16) {
            const __half* ar = &Tsh[g * TS_STRIDE + k0 + 2 * tig];
            unsigned a0 = *(const unsigned*)ar;
            unsigned a1 = *(const unsigned*)(ar + 8 * TS_STRIDE);
            unsigned a2 = *(const unsigned*)(ar + 8);
            unsigned a3 = *(const unsigned*)(ar + 8 * TS_STRIDE + 8);
            const __half* bp = W1s + (w * 8 + g) * P2_STRIDE + k0 + 2 * tig;
            unsigned b0 = *(const unsigned*)bp;
            unsigned b1r = *(const unsigned*)(bp + 8);
            mma_f16(dd, a0, a1, a2, a3, b0, b1r);
        }
        int col = w * 8 + 2 * tig;
        float2 bb = *(const float2*)&bp2[col];
        int r_lo = row0 + g;
        float2 lo, hi;
        lo.x = fmaxf(dd[0] + bb.x, 0.f);
        lo.y = fmaxf(dd[1] + bb.y, 0.f);
        hi.x = fmaxf(dd[2] + bb.x, 0.f);
        hi.y = fmaxf(dd[3] + bb.y, 0.f);
        *(float2*)&out[(size_t)r_lo * 64 + col] = lo;
        *(float2*)&out[(size_t)(r_lo + 8) * 64 + col] = hi;
    }
}

// ---------------- launch ----------------
extern "C" void kernel_launch(void* const* d_in, const int* in_sizes, int n_in,
                              void* d_out, int out_size) {
    const float* fm    = (const float*)d_in[0];
    const float* boxes = (const float*)d_in[1];
    const float* W1    = (const float*)d_in[2];
    const float* b1    = (const float*)d_in[3];
    const float* W2    = (const float*)d_in[4];
    const float* b2    = (const float*)d_in[5];
    const float* P1    = (const float*)d_in[6];
    const float* bp1   = (const float*)d_in[7];
    const float* P2    = (const float*)d_in[8];
    const float* bp2   = (const float*)d_in[9];
    float* out = (float*)d_out;

    cudaFuncSetAttribute(mlp_mma_kernel, cudaFuncAttributeMaxDynamicSharedMemorySize,
                         SMEM_MLP_BYTES);

    transpose_prep_kernel<<<NBT + 48, 256>>>(fm, W1, W2, P1, P2);
    pool_all_kernel<<<PB + 1, 256>>>(boxes, W1, b1, W2, b2, P1, bp1);
    mlp_mma_kernel<<<NROI / 16, 256, SMEM_MLP_BYTES>>>(b1, b2, bp2, out);
}